// round 4
// baseline (speedup 1.0000x reference)
#include <cuda_runtime.h>
#include <math.h>

#define BB 4
#define CC 64
#define WW 128
#define HH 128
#define KK 9
#define OCC 64
#define GG 16
#define EPSV 1e-5f

// Scratch (static device globals — no allocation allowed)
__device__ __align__(16) float g_fT[BB * WW * HH * CC];   // NHWC: ((b*W+y)*H+x)*C + c
__device__ __align__(16) float g_Wt[KK * CC * OCC];       // [k][c][oc]
__device__ __align__(16) int4   g_pidx[BB * KK * WW * HH]; // 4 corner base indices
__device__ __align__(16) float4 g_pwgt[BB * KK * WW * HH]; // 4 bilinear weights
__device__ float g_stats[BB * GG * 2];                    // (sum, sumsq) per (b, group)

// ---------------------------------------------------------------------------
// Kernel 0: NCHW -> NHWC transpose of f
// ---------------------------------------------------------------------------
__global__ void transpose_kernel(const float* __restrict__ f) {
    __shared__ float tile[32][33];
    const int by = blockIdx.x;          // b*128 + y
    const int b = by >> 7, y = by & 127;
    const int x0 = blockIdx.y * 32;
    const int c0 = blockIdx.z * 32;
    #pragma unroll
    for (int i = threadIdx.y; i < 32; i += 8) {
        tile[i][threadIdx.x] = f[((b * CC + c0 + i) * WW + y) * HH + x0 + threadIdx.x];
    }
    __syncthreads();
    #pragma unroll
    for (int i = threadIdx.y; i < 32; i += 8) {
        g_fT[((b * WW + y) * HH + x0 + i) * CC + c0 + threadIdx.x] = tile[threadIdx.x][i];
    }
}

// ---------------------------------------------------------------------------
// Kernel W: conv_w [oc][c][k] -> g_Wt [k][c][oc]
// ---------------------------------------------------------------------------
__global__ void wt_transpose_kernel(const float* __restrict__ conv_w) {
    int i = blockIdx.x * 256 + threadIdx.x;   // over 9*64*64
    if (i < KK * CC * OCC) {
        int k = i >> 12;
        int r = i & 4095;
        int c = r >> 6, oc = r & 63;
        g_Wt[i] = conv_w[(((oc << 6) + c) * KK) + k];
    }
}

// ---------------------------------------------------------------------------
// Kernel A: offset conv (9 of 18 out channels) + BN + tanh + partial cumsum
// -> bilinear corner indices + weights written straight to global tables.
// grid (B*W), block 128 (one thread per h).
// ---------------------------------------------------------------------------
__global__ void __launch_bounds__(128) offset_kernel(
    const float* __restrict__ f, const float* __restrict__ offset_w,
    const float* __restrict__ offset_b, const float* __restrict__ bn_gamma,
    const float* __restrict__ bn_beta, const float* __restrict__ bn_mean,
    const float* __restrict__ bn_var) {
    __shared__ float w_s[64 * 108];
    __shared__ float rows[3][8][128];

    const int bw = blockIdx.x;
    const int b = bw >> 7, w = bw & 127;
    const int h = threadIdx.x;

    for (int i = h; i < 9 * 64 * 9; i += 128) {
        int k = i / 576;
        int r = i - k * 576;
        int c = r / 9, tap = r - (r / 9) * 9;
        w_s[c * 108 + tap * 12 + k] = offset_w[(k * 64 + c) * 9 + tap];
    }

    float acc[9];
    #pragma unroll
    for (int k = 0; k < 9; k++) acc[k] = 0.f;

    for (int cc = 0; cc < 64; cc += 8) {
        __syncthreads();
        for (int i = h; i < 3 * 8 * 128; i += 128) {
            int dy = i / 1024;
            int rem = i - dy * 1024;
            int c = rem >> 7, hh = rem & 127;
            int wr = w + dy - 1;
            float v = 0.f;
            if (wr >= 0 && wr < WW) v = f[((b * CC + cc + c) * WW + wr) * HH + hh];
            rows[dy][c][hh] = v;
        }
        __syncthreads();
        #pragma unroll
        for (int c = 0; c < 8; c++) {
            const float* wb = &w_s[(cc + c) * 108];
            #pragma unroll
            for (int dy = 0; dy < 3; dy++) {
                float vm = (h > 0) ? rows[dy][c][h - 1] : 0.f;
                float vc = rows[dy][c][h];
                float vp = (h < 127) ? rows[dy][c][h + 1] : 0.f;
                #pragma unroll
                for (int dx = 0; dx < 3; dx++) {
                    float v = (dx == 0) ? vm : ((dx == 1) ? vc : vp);
                    const float* wp = wb + (dy * 3 + dx) * 12;
                    float4 w0 = *(const float4*)(wp);
                    float4 w1 = *(const float4*)(wp + 4);
                    float w8 = wp[8];
                    acc[0] = fmaf(v, w0.x, acc[0]);
                    acc[1] = fmaf(v, w0.y, acc[1]);
                    acc[2] = fmaf(v, w0.z, acc[2]);
                    acc[3] = fmaf(v, w0.w, acc[3]);
                    acc[4] = fmaf(v, w1.x, acc[4]);
                    acc[5] = fmaf(v, w1.y, acc[5]);
                    acc[6] = fmaf(v, w1.z, acc[6]);
                    acc[7] = fmaf(v, w1.w, acc[7]);
                    acc[8] = fmaf(v, w8, acc[8]);
                }
            }
        }
    }

    float off[9];
    #pragma unroll
    for (int k = 0; k < 9; k++) {
        float sc = bn_gamma[k] * rsqrtf(bn_var[k] + EPSV);
        off[k] = tanhf((acc[k] + offset_b[k] - bn_mean[k]) * sc + bn_beta[k]);
    }
    // partial cumsum exactly as reference: center=0, edges (0,8) stay raw
    float cum[9];
    cum[4] = 0.f;
    cum[0] = off[0];
    cum[8] = off[8];
    cum[5] = off[5];
    cum[6] = cum[5] + off[6];
    cum[7] = cum[6] + off[7];
    cum[3] = off[3];
    cum[2] = cum[3] + off[2];
    cum[1] = cum[2] + off[1];

    #pragma unroll
    for (int k = 0; k < 9; k++) {
        float ys = (float)w + cum[k];
        float xs = (float)h + (-5.0f + 1.125f * (float)k);   // linspace(-5,4,9)
        int y0 = (int)floorf(ys);
        y0 = max(0, min(y0, WW - 1));
        int y1 = min(y0 + 1, WW - 1);
        int x0 = (int)floorf(xs);
        x0 = max(0, min(x0, HH - 1));
        int x1 = min(x0 + 1, HH - 1);
        float wy1 = (float)y1 - ys;   // (y1f - ys)
        float wy0 = ys - (float)y0;   // (ys - y0f)
        float wx1 = (float)x1 - xs;
        float wx0 = xs - (float)x0;
        int4 ip;
        ip.x = ((b * WW + y0) * HH + x0) << 6;
        ip.y = ((b * WW + y0) * HH + x1) << 6;
        ip.z = ((b * WW + y1) * HH + x0) << 6;
        ip.w = ((b * WW + y1) * HH + x1) << 6;
        float4 wp;
        wp.x = wy1 * wx1;
        wp.y = wy1 * wx0;
        wp.z = wy0 * wx1;
        wp.w = wy0 * wx0;
        const int pidx = ((b * KK + k) * WW + w) * HH + h;
        g_pidx[pidx] = ip;
        g_pwgt[pidx] = wp;
    }
}

// ---------------------------------------------------------------------------
__global__ void zero_stats_kernel() {
    if (threadIdx.x < BB * GG * 2) g_stats[threadIdx.x] = 0.f;
}

// ---------------------------------------------------------------------------
// Kernel B: bilinear gather + (OC x C*K) conv + GN partial sums.
// grid (B*W), block 256. Thread = 8 oc x 4 h. Weights read via LDG from
// g_Wt (L1-resident); smem only for the gathered d tile (pitch 66 ->
// conflict-free scalar broadcasts in the GEMM).
// ---------------------------------------------------------------------------
__global__ void __launch_bounds__(256, 4) main_kernel(
    const float* __restrict__ conv_b, float* __restrict__ out) {
    __shared__ float dks[128 * 66];     // 33792 B

    const int bw = blockIdx.x;
    const int b = bw >> 7, w = bw & 127;
    const int tid = threadIdx.x;
    const int oc8 = tid & 7;            // oc base = oc8*8
    const int hq = tid >> 3;            // h base = hq*4 (0..124)
    const int hbase = hq << 2;

    float acc[32];                      // [j=0..3 h][q=0..7 oc]
    #pragma unroll
    for (int i = 0; i < 32; i++) acc[i] = 0.f;

    for (int k = 0; k < KK; k++) {
        __syncthreads();                // protect dks from previous GEMM reads
        // gather: 16 c-quads x 16 h per pass, 8 passes
        const int pbase = ((b * KK + k) * WW + w) * HH;
        const int cq4 = (tid & 15) << 2;
        #pragma unroll
        for (int pass = 0; pass < 8; pass++) {
            const int hg = (tid >> 4) + (pass << 4);
            const int4 ip = __ldg(&g_pidx[pbase + hg]);
            const float4 wp = __ldg(&g_pwgt[pbase + hg]);
            float4 v = *(const float4*)&g_fT[ip.x + cq4];
            float rx = v.x * wp.x, ry = v.y * wp.x, rz = v.z * wp.x, rw = v.w * wp.x;
            v = *(const float4*)&g_fT[ip.y + cq4];
            rx = fmaf(v.x, wp.y, rx); ry = fmaf(v.y, wp.y, ry);
            rz = fmaf(v.z, wp.y, rz); rw = fmaf(v.w, wp.y, rw);
            v = *(const float4*)&g_fT[ip.z + cq4];
            rx = fmaf(v.x, wp.z, rx); ry = fmaf(v.y, wp.z, ry);
            rz = fmaf(v.z, wp.z, rz); rw = fmaf(v.w, wp.z, rw);
            v = *(const float4*)&g_fT[ip.w + cq4];
            rx = fmaf(v.x, wp.w, rx); ry = fmaf(v.y, wp.w, ry);
            rz = fmaf(v.z, wp.w, rz); rw = fmaf(v.w, wp.w, rw);
            float* dp = &dks[hg * 66 + cq4];
            dp[0] = rx; dp[1] = ry; dp[2] = rz; dp[3] = rw;
        }
        __syncthreads();
        // GEMM accumulate: 8 oc x 4 h per thread
        const float* wkb = g_Wt + (k << 12) + (oc8 << 3);
        const float* dkb = dks + hbase * 66;
        #pragma unroll 4
        for (int c = 0; c < 64; c++) {
            const float4 wA = __ldg((const float4*)(wkb + (c << 6)));
            const float4 wB = __ldg((const float4*)(wkb + (c << 6) + 4));
            const float d0 = dkb[c];
            const float d1 = dkb[66 + c];
            const float d2 = dkb[132 + c];
            const float d3 = dkb[198 + c];
            acc[0]  = fmaf(d0, wA.x, acc[0]);
            acc[1]  = fmaf(d0, wA.y, acc[1]);
            acc[2]  = fmaf(d0, wA.z, acc[2]);
            acc[3]  = fmaf(d0, wA.w, acc[3]);
            acc[4]  = fmaf(d0, wB.x, acc[4]);
            acc[5]  = fmaf(d0, wB.y, acc[5]);
            acc[6]  = fmaf(d0, wB.z, acc[6]);
            acc[7]  = fmaf(d0, wB.w, acc[7]);
            acc[8]  = fmaf(d1, wA.x, acc[8]);
            acc[9]  = fmaf(d1, wA.y, acc[9]);
            acc[10] = fmaf(d1, wA.z, acc[10]);
            acc[11] = fmaf(d1, wA.w, acc[11]);
            acc[12] = fmaf(d1, wB.x, acc[12]);
            acc[13] = fmaf(d1, wB.y, acc[13]);
            acc[14] = fmaf(d1, wB.z, acc[14]);
            acc[15] = fmaf(d1, wB.w, acc[15]);
            acc[16] = fmaf(d2, wA.x, acc[16]);
            acc[17] = fmaf(d2, wA.y, acc[17]);
            acc[18] = fmaf(d2, wA.z, acc[18]);
            acc[19] = fmaf(d2, wA.w, acc[19]);
            acc[20] = fmaf(d2, wB.x, acc[20]);
            acc[21] = fmaf(d2, wB.y, acc[21]);
            acc[22] = fmaf(d2, wB.z, acc[22]);
            acc[23] = fmaf(d2, wB.w, acc[23]);
            acc[24] = fmaf(d3, wA.x, acc[24]);
            acc[25] = fmaf(d3, wA.y, acc[25]);
            acc[26] = fmaf(d3, wA.z, acc[26]);
            acc[27] = fmaf(d3, wA.w, acc[27]);
            acc[28] = fmaf(d3, wB.x, acc[28]);
            acc[29] = fmaf(d3, wB.y, acc[29]);
            acc[30] = fmaf(d3, wB.z, acc[30]);
            acc[31] = fmaf(d3, wB.w, acc[31]);
        }
    }

    // epilogue: bias, write z, GN partial sums.
    // Thread's 8 oc span two GN groups: oc8*2 (q 0..3) and oc8*2+1 (q 4..7).
    float s1a = 0.f, s2a = 0.f, s1b = 0.f, s2b = 0.f;
    #pragma unroll
    for (int q = 0; q < 8; q++) {
        const int oc = (oc8 << 3) + q;
        const float bias = conv_b[oc];
        float4 v;
        v.x = acc[0 + q] + bias;
        v.y = acc[8 + q] + bias;
        v.z = acc[16 + q] + bias;
        v.w = acc[24 + q] + bias;
        const float t1 = v.x + v.y + v.z + v.w;
        const float t2 = v.x * v.x + v.y * v.y + v.z * v.z + v.w * v.w;
        if (q < 4) { s1a += t1; s2a += t2; } else { s1b += t1; s2b += t2; }
        *(float4*)&out[((b * OCC + oc) * WW + w) * HH + hbase] = v;
    }
    const int g0 = oc8 << 1;
    atomicAdd(&g_stats[(b * GG + g0) * 2 + 0], s1a);
    atomicAdd(&g_stats[(b * GG + g0) * 2 + 1], s2a);
    atomicAdd(&g_stats[(b * GG + g0 + 1) * 2 + 0], s1b);
    atomicAdd(&g_stats[(b * GG + g0 + 1) * 2 + 1], s2b);
}

// ---------------------------------------------------------------------------
// Kernel C: GroupNorm finalize + ReLU (in place on out)
// ---------------------------------------------------------------------------
__global__ void __launch_bounds__(256) gn_kernel(float* __restrict__ out,
                                                 const float* __restrict__ gn_gamma,
                                                 const float* __restrict__ gn_beta) {
    const int idx = blockIdx.x * 256 + threadIdx.x;   // float4 index
    const int i4 = idx << 2;
    const int oc = (i4 >> 14) & 63;
    const int b = i4 >> 20;
    const int g = oc >> 2;
    const float inv = 1.0f / 65536.0f;
    float s1 = g_stats[(b * GG + g) * 2 + 0];
    float s2 = g_stats[(b * GG + g) * 2 + 1];
    float mean = s1 * inv;
    float var = s2 * inv - mean * mean;
    float sc = gn_gamma[oc] * rsqrtf(var + EPSV);
    float sh = gn_beta[oc] - mean * sc;
    float4* o4 = (float4*)out;
    float4 v = o4[idx];
    v.x = fmaxf(v.x * sc + sh, 0.f);
    v.y = fmaxf(v.y * sc + sh, 0.f);
    v.z = fmaxf(v.z * sc + sh, 0.f);
    v.w = fmaxf(v.w * sc + sh, 0.f);
    o4[idx] = v;
}

// ---------------------------------------------------------------------------
extern "C" void kernel_launch(void* const* d_in, const int* in_sizes, int n_in,
                              void* d_out, int out_size) {
    const float* f        = (const float*)d_in[0];
    const float* offset_w = (const float*)d_in[1];
    const float* offset_b = (const float*)d_in[2];
    const float* bn_gamma = (const float*)d_in[3];
    const float* bn_beta  = (const float*)d_in[4];
    const float* bn_mean  = (const float*)d_in[5];
    const float* bn_var   = (const float*)d_in[6];
    const float* conv_w   = (const float*)d_in[7];
    const float* conv_b   = (const float*)d_in[8];
    const float* gn_gamma = (const float*)d_in[9];
    const float* gn_beta  = (const float*)d_in[10];
    float* out = (float*)d_out;

    dim3 tgrid(BB * WW, HH / 32, CC / 32);
    dim3 tblk(32, 8);
    transpose_kernel<<<tgrid, tblk>>>(f);

    wt_transpose_kernel<<<(KK * CC * OCC + 255) / 256, 256>>>(conv_w);

    offset_kernel<<<BB * WW, 128>>>(f, offset_w, offset_b, bn_gamma, bn_beta,
                                    bn_mean, bn_var);

    zero_stats_kernel<<<1, 128>>>();

    main_kernel<<<BB * WW, 256>>>(conv_b, out);

    gn_kernel<<<(BB * OCC * WW * HH / 4) / 256, 256>>>(out, gn_gamma, gn_beta);
}

// round 6
// speedup vs baseline: 1.8195x; 1.8195x over previous
#include <cuda_runtime.h>
#include <math.h>

#define BB 4
#define CC 64
#define WW 128
#define HH 128
#define KK 9
#define OCC 64
#define GG 16
#define EPSV 1e-5f

// Scratch (static device globals — no allocation allowed)
__device__ __align__(16) float g_fT[BB * WW * HH * CC];    // NHWC
__device__ __align__(16) float g_Wt[KK * CC * OCC];        // [k][c][oc], tf32-rounded
__device__ __align__(16) int4   g_pidx[BB * KK * WW * HH]; // 4 corner base indices
__device__ __align__(16) float4 g_pwgt[BB * KK * WW * HH]; // 4 bilinear weights
__device__ float g_stats[BB * GG * 2];                     // (sum, sumsq)

__device__ __forceinline__ unsigned int f2tf32(float x) {
    unsigned int u;
    asm("cvt.rna.tf32.f32 %0, %1;" : "=r"(u) : "f"(x));
    return u;
}

// ---------------------------------------------------------------------------
// Kernel 0: NCHW -> NHWC transpose of f
// ---------------------------------------------------------------------------
__global__ void transpose_kernel(const float* __restrict__ f) {
    __shared__ float tile[32][33];
    const int by = blockIdx.x;
    const int b = by >> 7, y = by & 127;
    const int x0 = blockIdx.y * 32;
    const int c0 = blockIdx.z * 32;
    #pragma unroll
    for (int i = threadIdx.y; i < 32; i += 8) {
        tile[i][threadIdx.x] = f[((b * CC + c0 + i) * WW + y) * HH + x0 + threadIdx.x];
    }
    __syncthreads();
    #pragma unroll
    for (int i = threadIdx.y; i < 32; i += 8) {
        g_fT[((b * WW + y) * HH + x0 + i) * CC + c0 + threadIdx.x] = tile[threadIdx.x][i];
    }
}

// ---------------------------------------------------------------------------
// Kernel W: conv_w [oc][c][k] -> g_Wt [k][c][oc], rounded to tf32
// ---------------------------------------------------------------------------
__global__ void wt_transpose_kernel(const float* __restrict__ conv_w) {
    int i = blockIdx.x * 256 + threadIdx.x;
    if (i < KK * CC * OCC) {
        int k = i >> 12;
        int r = i & 4095;
        int c = r >> 6, oc = r & 63;
        g_Wt[i] = __uint_as_float(f2tf32(conv_w[(((oc << 6) + c) * KK) + k]));
    }
}

// ---------------------------------------------------------------------------
// Kernel A: offset conv (9 of 18 oc) + BN + tanh + partial cumsum ->
// bilinear corner indices + weights. grid (B*W), block 128.
// ---------------------------------------------------------------------------
__global__ void __launch_bounds__(128) offset_kernel(
    const float* __restrict__ f, const float* __restrict__ offset_w,
    const float* __restrict__ offset_b, const float* __restrict__ bn_gamma,
    const float* __restrict__ bn_beta, const float* __restrict__ bn_mean,
    const float* __restrict__ bn_var) {
    __shared__ float w_s[64 * 108];
    __shared__ float rows[3][8][128];

    const int bw = blockIdx.x;
    const int b = bw >> 7, w = bw & 127;
    const int h = threadIdx.x;

    for (int i = h; i < 9 * 64 * 9; i += 128) {
        int k = i / 576;
        int r = i - k * 576;
        int c = r / 9, tap = r - (r / 9) * 9;
        w_s[c * 108 + tap * 12 + k] = offset_w[(k * 64 + c) * 9 + tap];
    }

    float acc[9];
    #pragma unroll
    for (int k = 0; k < 9; k++) acc[k] = 0.f;

    for (int cc = 0; cc < 64; cc += 8) {
        __syncthreads();
        for (int i = h; i < 3 * 8 * 128; i += 128) {
            int dy = i / 1024;
            int rem = i - dy * 1024;
            int c = rem >> 7, hh = rem & 127;
            int wr = w + dy - 1;
            float v = 0.f;
            if (wr >= 0 && wr < WW) v = f[((b * CC + cc + c) * WW + wr) * HH + hh];
            rows[dy][c][hh] = v;
        }
        __syncthreads();
        #pragma unroll
        for (int c = 0; c < 8; c++) {
            const float* wb = &w_s[(cc + c) * 108];
            #pragma unroll
            for (int dy = 0; dy < 3; dy++) {
                float vm = (h > 0) ? rows[dy][c][h - 1] : 0.f;
                float vc = rows[dy][c][h];
                float vp = (h < 127) ? rows[dy][c][h + 1] : 0.f;
                #pragma unroll
                for (int dx = 0; dx < 3; dx++) {
                    float v = (dx == 0) ? vm : ((dx == 1) ? vc : vp);
                    const float* wp = wb + (dy * 3 + dx) * 12;
                    float4 w0 = *(const float4*)(wp);
                    float4 w1 = *(const float4*)(wp + 4);
                    float w8 = wp[8];
                    acc[0] = fmaf(v, w0.x, acc[0]);
                    acc[1] = fmaf(v, w0.y, acc[1]);
                    acc[2] = fmaf(v, w0.z, acc[2]);
                    acc[3] = fmaf(v, w0.w, acc[3]);
                    acc[4] = fmaf(v, w1.x, acc[4]);
                    acc[5] = fmaf(v, w1.y, acc[5]);
                    acc[6] = fmaf(v, w1.z, acc[6]);
                    acc[7] = fmaf(v, w1.w, acc[7]);
                    acc[8] = fmaf(v, w8, acc[8]);
                }
            }
        }
    }

    float off[9];
    #pragma unroll
    for (int k = 0; k < 9; k++) {
        float sc = bn_gamma[k] * rsqrtf(bn_var[k] + EPSV);
        off[k] = tanhf((acc[k] + offset_b[k] - bn_mean[k]) * sc + bn_beta[k]);
    }
    float cum[9];
    cum[4] = 0.f;
    cum[0] = off[0];
    cum[8] = off[8];
    cum[5] = off[5];
    cum[6] = cum[5] + off[6];
    cum[7] = cum[6] + off[7];
    cum[3] = off[3];
    cum[2] = cum[3] + off[2];
    cum[1] = cum[2] + off[1];

    #pragma unroll
    for (int k = 0; k < 9; k++) {
        float ys = (float)w + cum[k];
        float xs = (float)h + (-5.0f + 1.125f * (float)k);   // linspace(-5,4,9)
        int y0 = (int)floorf(ys);
        y0 = max(0, min(y0, WW - 1));
        int y1 = min(y0 + 1, WW - 1);
        int x0 = (int)floorf(xs);
        x0 = max(0, min(x0, HH - 1));
        int x1 = min(x0 + 1, HH - 1);
        float wy1 = (float)y1 - ys;
        float wy0 = ys - (float)y0;
        float wx1 = (float)x1 - xs;
        float wx0 = xs - (float)x0;
        int4 ip;
        ip.x = ((b * WW + y0) * HH + x0) << 6;
        ip.y = ((b * WW + y0) * HH + x1) << 6;
        ip.z = ((b * WW + y1) * HH + x0) << 6;
        ip.w = ((b * WW + y1) * HH + x1) << 6;
        float4 wp;
        wp.x = wy1 * wx1;
        wp.y = wy1 * wx0;
        wp.z = wy0 * wx1;
        wp.w = wy0 * wx0;
        const int pidx = ((b * KK + k) * WW + w) * HH + h;
        g_pidx[pidx] = ip;
        g_pwgt[pidx] = wp;
    }
}

// ---------------------------------------------------------------------------
__global__ void zero_stats_kernel() {
    if (threadIdx.x < BB * GG * 2) g_stats[threadIdx.x] = 0.f;
}

// ---------------------------------------------------------------------------
// Kernel B: bilinear gather + TF32 tensor-core GEMM + GN partial sums.
// grid (B*W), block 256 (8 warps). Warp wid owns D rows h in [wid*16, +16).
// smem: Wt[c][oc] pitch 72 (B frags bank-clean), dks[h][c] pitch 68
// (A frags bank-clean); dks reused as zbuf[oc][h] pitch 136 in epilogue.
// ---------------------------------------------------------------------------
#define WTP 72
#define DKP 68
#define ZBP 136

__global__ void __launch_bounds__(256, 3) main_kernel(
    const float* __restrict__ conv_b, float* __restrict__ out) {
    extern __shared__ float sm[];
    float* wt_s = sm;                    // 64*72 = 4608 floats
    float* dks = sm + 64 * WTP;          // 128*68 = 8704 floats (= zbuf 64*136)

    const int bw = blockIdx.x;
    const int b = bw >> 7, w = bw & 127;
    const int tid = threadIdx.x;
    const int lane = tid & 31;
    const int wid = tid >> 5;
    const int g = lane >> 2, t = lane & 3;
    const int h0 = wid << 4;

    float acc[8][4];
    #pragma unroll
    for (int n = 0; n < 8; n++)
        #pragma unroll
        for (int j = 0; j < 4; j++) acc[n][j] = 0.f;

    const int cq4 = (tid & 15) << 2;

    for (int k = 0; k < KK; k++) {
        __syncthreads();
        // stage Wt[c][oc] (already tf32-rounded in g_Wt)
        #pragma unroll
        for (int j = 0; j < 4; j++) {
            int i4 = tid + j * 256;              // 0..1023 float4s
            int c = i4 >> 4, oc4 = (i4 & 15) << 2;
            float4 v = *(const float4*)&g_Wt[(k << 12) + (c << 6) + oc4];
            *(float4*)&wt_s[c * WTP + oc4] = v;
        }
        // gather -> dks[h][c] (tf32-rounded)
        const int pbase = ((b * KK + k) * WW + w) * HH;
        #pragma unroll
        for (int pass = 0; pass < 8; pass++) {
            const int hg = (tid >> 4) + (pass << 4);
            const int4 ip = __ldg(&g_pidx[pbase + hg]);
            const float4 wp = __ldg(&g_pwgt[pbase + hg]);
            float4 v = *(const float4*)&g_fT[ip.x + cq4];
            float rx = v.x * wp.x, ry = v.y * wp.x, rz = v.z * wp.x, rw = v.w * wp.x;
            v = *(const float4*)&g_fT[ip.y + cq4];
            rx = fmaf(v.x, wp.y, rx); ry = fmaf(v.y, wp.y, ry);
            rz = fmaf(v.z, wp.y, rz); rw = fmaf(v.w, wp.y, rw);
            v = *(const float4*)&g_fT[ip.z + cq4];
            rx = fmaf(v.x, wp.z, rx); ry = fmaf(v.y, wp.z, ry);
            rz = fmaf(v.z, wp.z, rz); rw = fmaf(v.w, wp.z, rw);
            v = *(const float4*)&g_fT[ip.w + cq4];
            rx = fmaf(v.x, wp.w, rx); ry = fmaf(v.y, wp.w, ry);
            rz = fmaf(v.z, wp.w, rz); rw = fmaf(v.w, wp.w, rw);
            float4 r;
            r.x = __uint_as_float(f2tf32(rx));
            r.y = __uint_as_float(f2tf32(ry));
            r.z = __uint_as_float(f2tf32(rz));
            r.w = __uint_as_float(f2tf32(rw));
            *(float4*)&dks[hg * DKP + cq4] = r;
        }
        __syncthreads();
        // tensor GEMM: warp tile m16(h) x n64(oc), K=64 in 8 chunks
        const unsigned int* dku = (const unsigned int*)dks;
        const unsigned int* wtu = (const unsigned int*)wt_s;
        #pragma unroll
        for (int kc = 0; kc < 8; kc++) {
            const int ca = (kc << 3) + t;
            unsigned int a0 = dku[(h0 + g) * DKP + ca];
            unsigned int a1 = dku[(h0 + g + 8) * DKP + ca];
            unsigned int a2 = dku[(h0 + g) * DKP + ca + 4];
            unsigned int a3 = dku[(h0 + g + 8) * DKP + ca + 4];
            #pragma unroll
            for (int n = 0; n < 8; n++) {
                unsigned int b0 = wtu[ca * WTP + (n << 3) + g];
                unsigned int b1 = wtu[(ca + 4) * WTP + (n << 3) + g];
                asm("mma.sync.aligned.m16n8k8.row.col.f32.tf32.tf32.f32 "
                    "{%0,%1,%2,%3}, {%4,%5,%6,%7}, {%8,%9}, {%0,%1,%2,%3};"
                    : "+f"(acc[n][0]), "+f"(acc[n][1]), "+f"(acc[n][2]), "+f"(acc[n][3])
                    : "r"(a0), "r"(a1), "r"(a2), "r"(a3), "r"(b0), "r"(b1));
            }
        }
    }

    // epilogue: D frags -> smem zbuf[oc][h] -> coalesced out + GN stats
    __syncthreads();
    float* zbuf = dks;                   // 64 x 136
    #pragma unroll
    for (int n = 0; n < 8; n++) {
        const int oc = (n << 3) + (t << 1);
        zbuf[oc * ZBP + h0 + g] = acc[n][0];
        zbuf[(oc + 1) * ZBP + h0 + g] = acc[n][1];
        zbuf[oc * ZBP + h0 + g + 8] = acc[n][2];
        zbuf[(oc + 1) * ZBP + h0 + g + 8] = acc[n][3];
    }
    __syncthreads();
    const int oc = tid >> 2;
    const int hq = (tid & 3) << 5;
    const float bias = conv_b[oc];
    float s1 = 0.f, s2 = 0.f;
    float* op = out + ((b * OCC + oc) * WW + w) * HH + hq;
    #pragma unroll
    for (int j = 0; j < 8; j++) {
        float4 v = *(float4*)&zbuf[oc * ZBP + hq + (j << 2)];
        v.x += bias; v.y += bias; v.z += bias; v.w += bias;
        s1 += v.x + v.y + v.z + v.w;
        s2 += v.x * v.x + v.y * v.y + v.z * v.z + v.w * v.w;
        *(float4*)&op[j << 2] = v;
    }
    // reduce within oc (xor 1,2) then within group of 4 ocs (xor 4,8)
    #pragma unroll
    for (int m = 1; m <= 8; m <<= 1) {
        s1 += __shfl_xor_sync(0xffffffffu, s1, m);
        s2 += __shfl_xor_sync(0xffffffffu, s2, m);
    }
    if ((lane & 15) == 0) {
        const int grp = oc >> 2;
        atomicAdd(&g_stats[(b * GG + grp) * 2 + 0], s1);
        atomicAdd(&g_stats[(b * GG + grp) * 2 + 1], s2);
    }
}

// ---------------------------------------------------------------------------
// Kernel C: GroupNorm finalize + ReLU (in place on out)
// ---------------------------------------------------------------------------
__global__ void __launch_bounds__(256) gn_kernel(float* __restrict__ out,
                                                 const float* __restrict__ gn_gamma,
                                                 const float* __restrict__ gn_beta) {
    const int idx = blockIdx.x * 256 + threadIdx.x;
    const int i4 = idx << 2;
    const int oc = (i4 >> 14) & 63;
    const int b = i4 >> 20;
    const int g = oc >> 2;
    const float inv = 1.0f / 65536.0f;
    float s1 = g_stats[(b * GG + g) * 2 + 0];
    float s2 = g_stats[(b * GG + g) * 2 + 1];
    float mean = s1 * inv;
    float var = s2 * inv - mean * mean;
    float sc = gn_gamma[oc] * rsqrtf(var + EPSV);
    float sh = gn_beta[oc] - mean * sc;
    float4* o4 = (float4*)out;
    float4 v = o4[idx];
    v.x = fmaxf(v.x * sc + sh, 0.f);
    v.y = fmaxf(v.y * sc + sh, 0.f);
    v.z = fmaxf(v.z * sc + sh, 0.f);
    v.w = fmaxf(v.w * sc + sh, 0.f);
    o4[idx] = v;
}

// ---------------------------------------------------------------------------
extern "C" void kernel_launch(void* const* d_in, const int* in_sizes, int n_in,
                              void* d_out, int out_size) {
    const float* f        = (const float*)d_in[0];
    const float* offset_w = (const float*)d_in[1];
    const float* offset_b = (const float*)d_in[2];
    const float* bn_gamma = (const float*)d_in[3];
    const float* bn_beta  = (const float*)d_in[4];
    const float* bn_mean  = (const float*)d_in[5];
    const float* bn_var   = (const float*)d_in[6];
    const float* conv_w   = (const float*)d_in[7];
    const float* conv_b   = (const float*)d_in[8];
    const float* gn_gamma = (const float*)d_in[9];
    const float* gn_beta  = (const float*)d_in[10];
    float* out = (float*)d_out;

    const int main_smem = (64 * WTP + 128 * DKP) * 4;   // 53248 bytes
    cudaFuncSetAttribute(main_kernel, cudaFuncAttributeMaxDynamicSharedMemorySize,
                         main_smem);

    dim3 tgrid(BB * WW, HH / 32, CC / 32);
    dim3 tblk(32, 8);
    transpose_kernel<<<tgrid, tblk>>>(f);

    wt_transpose_kernel<<<(KK * CC * OCC + 255) / 256, 256>>>(conv_w);

    offset_kernel<<<BB * WW, 128>>>(f, offset_w, offset_b, bn_gamma, bn_beta,
                                    bn_mean, bn_var);

    zero_stats_kernel<<<1, 128>>>();

    main_kernel<<<BB * WW, 256, main_smem>>>(conv_b, out);

    gn_kernel<<<(BB * OCC * WW * HH / 4) / 256, 256>>>(out, gn_gamma, gn_beta);
}

// round 9
// speedup vs baseline: 2.0258x; 1.1134x over previous
#include <cuda_runtime.h>
#include <cuda_fp16.h>
#include <math.h>

#define BB 4
#define CC 64
#define WW 128
#define HH 128
#define KK 9
#define OCC 64
#define GG 16
#define EPSV 1e-5f

// Scratch (static device globals — no allocation allowed)
__device__ __align__(16) float g_fT[BB * WW * HH * CC];    // NHWC
__device__ __align__(16) unsigned int g_Wt2[KK * 32 * OCC]; // [k][c2][oc] half2 (c pairs)
__device__ __align__(16) int4   g_pidx[BB * KK * WW * HH]; // 4 corner base indices
__device__ __align__(16) float4 g_pwgt[BB * KK * WW * HH]; // 4 bilinear weights
__device__ float g_stats[BB * GG * 2];                     // (sum, sumsq)

// ---------------------------------------------------------------------------
// Kernel 0: NCHW -> NHWC transpose of f
// ---------------------------------------------------------------------------
__global__ void transpose_kernel(const float* __restrict__ f) {
    __shared__ float tile[32][33];
    const int by = blockIdx.x;
    const int b = by >> 7, y = by & 127;
    const int x0 = blockIdx.y * 32;
    const int c0 = blockIdx.z * 32;
    #pragma unroll
    for (int i = threadIdx.y; i < 32; i += 8) {
        tile[i][threadIdx.x] = f[((b * CC + c0 + i) * WW + y) * HH + x0 + threadIdx.x];
    }
    __syncthreads();
    #pragma unroll
    for (int i = threadIdx.y; i < 32; i += 8) {
        g_fT[((b * WW + y) * HH + x0 + i) * CC + c0 + threadIdx.x] = tile[threadIdx.x][i];
    }
}

// ---------------------------------------------------------------------------
// Kernel W: conv_w [oc][c][k] -> g_Wt2 [k][c2][oc] as half2 (c even = low).
// Also zeroes the GN stat accumulators (block 0).
// ---------------------------------------------------------------------------
__global__ void wt_pack_kernel(const float* __restrict__ conv_w) {
    int i = blockIdx.x * 256 + threadIdx.x;   // over 9*32*64 = 18432
    if (i < KK * 32 * OCC) {
        int k = i / 2048;
        int r = i & 2047;
        int c2 = r >> 6, oc = r & 63;
        float w0 = conv_w[(((oc << 6) + (c2 << 1)) * KK) + k];
        float w1 = conv_w[(((oc << 6) + (c2 << 1) + 1) * KK) + k];
        __half2 p = __floats2half2_rn(w0, w1);
        g_Wt2[i] = *(unsigned int*)&p;
    }
    if (blockIdx.x == 0 && threadIdx.x < BB * GG * 2) g_stats[threadIdx.x] = 0.f;
}

// ---------------------------------------------------------------------------
// Kernel A: offset conv (9 of 18 oc) + BN + tanh + partial cumsum ->
// bilinear corner indices + weights. grid (B*W), block 128.
// ---------------------------------------------------------------------------
__global__ void __launch_bounds__(128) offset_kernel(
    const float* __restrict__ f, const float* __restrict__ offset_w,
    const float* __restrict__ offset_b, const float* __restrict__ bn_gamma,
    const float* __restrict__ bn_beta, const float* __restrict__ bn_mean,
    const float* __restrict__ bn_var) {
    __shared__ float w_s[64 * 108];
    __shared__ float rows[3][8][128];

    const int bw = blockIdx.x;
    const int b = bw >> 7, w = bw & 127;
    const int h = threadIdx.x;

    for (int i = h; i < 9 * 64 * 9; i += 128) {
        int k = i / 576;
        int r = i - k * 576;
        int c = r / 9, tap = r - (r / 9) * 9;
        w_s[c * 108 + tap * 12 + k] = offset_w[(k * 64 + c) * 9 + tap];
    }

    float acc[9];
    #pragma unroll
    for (int k = 0; k < 9; k++) acc[k] = 0.f;

    for (int cc = 0; cc < 64; cc += 8) {
        __syncthreads();
        for (int i = h; i < 3 * 8 * 128; i += 128) {
            int dy = i / 1024;
            int rem = i - dy * 1024;
            int c = rem >> 7, hh = rem & 127;
            int wr = w + dy - 1;
            float v = 0.f;
            if (wr >= 0 && wr < WW) v = f[((b * CC + cc + c) * WW + wr) * HH + hh];
            rows[dy][c][hh] = v;
        }
        __syncthreads();
        #pragma unroll
        for (int c = 0; c < 8; c++) {
            const float* wb = &w_s[(cc + c) * 108];
            #pragma unroll
            for (int dy = 0; dy < 3; dy++) {
                float vm = (h > 0) ? rows[dy][c][h - 1] : 0.f;
                float vc = rows[dy][c][h];
                float vp = (h < 127) ? rows[dy][c][h + 1] : 0.f;
                #pragma unroll
                for (int dx = 0; dx < 3; dx++) {
                    float v = (dx == 0) ? vm : ((dx == 1) ? vc : vp);
                    const float* wp = wb + (dy * 3 + dx) * 12;
                    float4 w0 = *(const float4*)(wp);
                    float4 w1 = *(const float4*)(wp + 4);
                    float w8 = wp[8];
                    acc[0] = fmaf(v, w0.x, acc[0]);
                    acc[1] = fmaf(v, w0.y, acc[1]);
                    acc[2] = fmaf(v, w0.z, acc[2]);
                    acc[3] = fmaf(v, w0.w, acc[3]);
                    acc[4] = fmaf(v, w1.x, acc[4]);
                    acc[5] = fmaf(v, w1.y, acc[5]);
                    acc[6] = fmaf(v, w1.z, acc[6]);
                    acc[7] = fmaf(v, w1.w, acc[7]);
                    acc[8] = fmaf(v, w8, acc[8]);
                }
            }
        }
    }

    float off[9];
    #pragma unroll
    for (int k = 0; k < 9; k++) {
        float sc = bn_gamma[k] * rsqrtf(bn_var[k] + EPSV);
        off[k] = tanhf((acc[k] + offset_b[k] - bn_mean[k]) * sc + bn_beta[k]);
    }
    float cum[9];
    cum[4] = 0.f;
    cum[0] = off[0];
    cum[8] = off[8];
    cum[5] = off[5];
    cum[6] = cum[5] + off[6];
    cum[7] = cum[6] + off[7];
    cum[3] = off[3];
    cum[2] = cum[3] + off[2];
    cum[1] = cum[2] + off[1];

    #pragma unroll
    for (int k = 0; k < 9; k++) {
        float ys = (float)w + cum[k];
        float xs = (float)h + (-5.0f + 1.125f * (float)k);   // linspace(-5,4,9)
        int y0 = (int)floorf(ys);
        y0 = max(0, min(y0, WW - 1));
        int y1 = min(y0 + 1, WW - 1);
        int x0 = (int)floorf(xs);
        x0 = max(0, min(x0, HH - 1));
        int x1 = min(x0 + 1, HH - 1);
        float wy1 = (float)y1 - ys;
        float wy0 = ys - (float)y0;
        float wx1 = (float)x1 - xs;
        float wx0 = xs - (float)x0;
        int4 ip;
        ip.x = ((b * WW + y0) * HH + x0) << 6;
        ip.y = ((b * WW + y0) * HH + x1) << 6;
        ip.z = ((b * WW + y1) * HH + x0) << 6;
        ip.w = ((b * WW + y1) * HH + x1) << 6;
        float4 wp;
        wp.x = wy1 * wx1;
        wp.y = wy1 * wx0;
        wp.z = wy0 * wx1;
        wp.w = wy0 * wx0;
        const int pidx = ((b * KK + k) * WW + w) * HH + h;
        g_pidx[pidx] = ip;
        g_pwgt[pidx] = wp;
    }
}

// ---------------------------------------------------------------------------
// Kernel B: bilinear gather + FP16 tensor-core GEMM + GN partial sums.
// grid (B*W), block 256 (8 warps). Warp tile m32(h) x n32(oc),
// mma.m16n8k16.f16 with fp32 accumulators.
// smem: wt2[c2][oc] uints pitch 72 (B frags bank-clean),
//       dksh[h][c] halves pitch 72 (A frags bank-clean);
//       reused as zbuf[oc][h] floats pitch 132 in the epilogue.
// ---------------------------------------------------------------------------
#define WTP2 72
#define DKPH 72
#define ZBP 132

__global__ void __launch_bounds__(256, 3) main_kernel(
    const float* __restrict__ conv_b, float* __restrict__ out) {
    extern __shared__ char smc[];
    unsigned int* wt2 = (unsigned int*)smc;            // 32*72 uints = 9216 B
    unsigned short* dksh = (unsigned short*)(smc + 9216); // 128*72 halves = 18432 B
    unsigned int* dku = (unsigned int*)dksh;           // row pitch 36 uints
    float* zbuf = (float*)smc;                         // epilogue: 64*132 floats

    const int bw = blockIdx.x;
    const int b = bw >> 7, w = bw & 127;
    const int tid = threadIdx.x;
    const int lane = tid & 31;
    const int wid = tid >> 5;
    const int g = lane >> 2, t = lane & 3;
    const int h0 = (wid & 3) << 5;        // m32 tile
    const int n0 = (wid >> 2) << 5;       // n32 tile

    float acc[2][4][4];
    #pragma unroll
    for (int mi = 0; mi < 2; mi++)
        #pragma unroll
        for (int nj = 0; nj < 4; nj++)
            #pragma unroll
            for (int j = 0; j < 4; j++) acc[mi][nj][j] = 0.f;

    const int cq4 = (tid & 15) << 2;

    for (int k = 0; k < KK; k++) {
        __syncthreads();
        // stage weights: exactly 512 uint4s from g_Wt2[k] (R7 bug: guard was
        // <576, overrunning into dksh and racing with the gather)
        #pragma unroll
        for (int j = 0; j < 2; j++) {
            int i4 = tid + (j << 8);                 // 0..511
            int c2 = i4 >> 4, oc4 = (i4 & 15) << 2;
            *(uint4*)&wt2[c2 * WTP2 + oc4] =
                ((const uint4*)g_Wt2)[(k << 9) + i4];
        }
        // gather -> dksh[h][c] fp16
        const int pbase = ((b * KK + k) * WW + w) * HH;
        #pragma unroll
        for (int pass = 0; pass < 8; pass++) {
            const int hg = (tid >> 4) + (pass << 4);
            const int4 ip = __ldg(&g_pidx[pbase + hg]);
            const float4 wp = __ldg(&g_pwgt[pbase + hg]);
            float4 v = *(const float4*)&g_fT[ip.x + cq4];
            float rx = v.x * wp.x, ry = v.y * wp.x, rz = v.z * wp.x, rw = v.w * wp.x;
            v = *(const float4*)&g_fT[ip.y + cq4];
            rx = fmaf(v.x, wp.y, rx); ry = fmaf(v.y, wp.y, ry);
            rz = fmaf(v.z, wp.y, rz); rw = fmaf(v.w, wp.y, rw);
            v = *(const float4*)&g_fT[ip.z + cq4];
            rx = fmaf(v.x, wp.z, rx); ry = fmaf(v.y, wp.z, ry);
            rz = fmaf(v.z, wp.z, rz); rw = fmaf(v.w, wp.z, rw);
            v = *(const float4*)&g_fT[ip.w + cq4];
            rx = fmaf(v.x, wp.w, rx); ry = fmaf(v.y, wp.w, ry);
            rz = fmaf(v.z, wp.w, rz); rw = fmaf(v.w, wp.w, rw);
            __half2 p0 = __floats2half2_rn(rx, ry);   // low = even c
            __half2 p1 = __floats2half2_rn(rz, rw);
            uint2 pk;
            pk.x = *(unsigned int*)&p0;
            pk.y = *(unsigned int*)&p1;
            *(uint2*)&dksh[hg * DKPH + cq4] = pk;
        }
        __syncthreads();
        // MMA: warp tile m32 x n32, K=64 halves in 4 k16 chunks
        #pragma unroll
        for (int kc = 0; kc < 4; kc++) {
            const int ka = kc << 3;               // uint offset in dks row
            unsigned int a[2][4];
            #pragma unroll
            for (int mi = 0; mi < 2; mi++) {
                const int hb = h0 + (mi << 4);
                a[mi][0] = dku[(hb + g) * 36 + ka + t];
                a[mi][1] = dku[(hb + g + 8) * 36 + ka + t];
                a[mi][2] = dku[(hb + g) * 36 + ka + t + 4];
                a[mi][3] = dku[(hb + g + 8) * 36 + ka + t + 4];
            }
            #pragma unroll
            for (int nj = 0; nj < 4; nj++) {
                const int ncol = n0 + (nj << 3) + g;
                unsigned int b0 = wt2[(ka + t) * WTP2 + ncol];
                unsigned int b1 = wt2[(ka + t + 4) * WTP2 + ncol];
                #pragma unroll
                for (int mi = 0; mi < 2; mi++) {
                    asm("mma.sync.aligned.m16n8k16.row.col.f32.f16.f16.f32 "
                        "{%0,%1,%2,%3}, {%4,%5,%6,%7}, {%8,%9}, {%0,%1,%2,%3};"
                        : "+f"(acc[mi][nj][0]), "+f"(acc[mi][nj][1]),
                          "+f"(acc[mi][nj][2]), "+f"(acc[mi][nj][3])
                        : "r"(a[mi][0]), "r"(a[mi][1]), "r"(a[mi][2]), "r"(a[mi][3]),
                          "r"(b0), "r"(b1));
                }
            }
        }
    }

    // epilogue: fragments -> zbuf[oc][h] -> coalesced out + GN stats
    __syncthreads();
    #pragma unroll
    for (int mi = 0; mi < 2; mi++) {
        #pragma unroll
        for (int nj = 0; nj < 4; nj++) {
            const int oc = n0 + (nj << 3) + (t << 1);
            const int hh = h0 + (mi << 4) + g;
            zbuf[oc * ZBP + hh] = acc[mi][nj][0];
            zbuf[(oc + 1) * ZBP + hh] = acc[mi][nj][1];
            zbuf[oc * ZBP + hh + 8] = acc[mi][nj][2];
            zbuf[(oc + 1) * ZBP + hh + 8] = acc[mi][nj][3];
        }
    }
    __syncthreads();
    const int oc = tid >> 2;
    const int hq = (tid & 3) << 5;
    const float bias = conv_b[oc];
    float s1 = 0.f, s2 = 0.f;
    float* op = out + ((b * OCC + oc) * WW + w) * HH + hq;
    #pragma unroll
    for (int j = 0; j < 8; j++) {
        float4 v = *(float4*)&zbuf[oc * ZBP + hq + (j << 2)];
        v.x += bias; v.y += bias; v.z += bias; v.w += bias;
        s1 += v.x + v.y + v.z + v.w;
        s2 += v.x * v.x + v.y * v.y + v.z * v.z + v.w * v.w;
        *(float4*)&op[j << 2] = v;
    }
    #pragma unroll
    for (int m = 1; m <= 8; m <<= 1) {
        s1 += __shfl_xor_sync(0xffffffffu, s1, m);
        s2 += __shfl_xor_sync(0xffffffffu, s2, m);
    }
    if ((lane & 15) == 0) {
        const int grp = oc >> 2;
        atomicAdd(&g_stats[(b * GG + grp) * 2 + 0], s1);
        atomicAdd(&g_stats[(b * GG + grp) * 2 + 1], s2);
    }
}

// ---------------------------------------------------------------------------
// Kernel C: GroupNorm finalize + ReLU (in place on out)
// ---------------------------------------------------------------------------
__global__ void __launch_bounds__(256) gn_kernel(float* __restrict__ out,
                                                 const float* __restrict__ gn_gamma,
                                                 const float* __restrict__ gn_beta) {
    const int idx = blockIdx.x * 256 + threadIdx.x;
    const int i4 = idx << 2;
    const int oc = (i4 >> 14) & 63;
    const int b = i4 >> 20;
    const int g = oc >> 2;
    const float inv = 1.0f / 65536.0f;
    float s1 = g_stats[(b * GG + g) * 2 + 0];
    float s2 = g_stats[(b * GG + g) * 2 + 1];
    float mean = s1 * inv;
    float var = s2 * inv - mean * mean;
    float sc = gn_gamma[oc] * rsqrtf(var + EPSV);
    float sh = gn_beta[oc] - mean * sc;
    float4* o4 = (float4*)out;
    float4 v = o4[idx];
    v.x = fmaxf(v.x * sc + sh, 0.f);
    v.y = fmaxf(v.y * sc + sh, 0.f);
    v.z = fmaxf(v.z * sc + sh, 0.f);
    v.w = fmaxf(v.w * sc + sh, 0.f);
    o4[idx] = v;
}

// ---------------------------------------------------------------------------
extern "C" void kernel_launch(void* const* d_in, const int* in_sizes, int n_in,
                              void* d_out, int out_size) {
    const float* f        = (const float*)d_in[0];
    const float* offset_w = (const float*)d_in[1];
    const float* offset_b = (const float*)d_in[2];
    const float* bn_gamma = (const float*)d_in[3];
    const float* bn_beta  = (const float*)d_in[4];
    const float* bn_mean  = (const float*)d_in[5];
    const float* bn_var   = (const float*)d_in[6];
    const float* conv_w   = (const float*)d_in[7];
    const float* conv_b   = (const float*)d_in[8];
    const float* gn_gamma = (const float*)d_in[9];
    const float* gn_beta  = (const float*)d_in[10];
    float* out = (float*)d_out;

    const int main_smem = 64 * ZBP * 4;   // 33792 bytes (>= 9216 + 18432)
    cudaFuncSetAttribute(main_kernel, cudaFuncAttributeMaxDynamicSharedMemorySize,
                         main_smem);

    dim3 tgrid(BB * WW, HH / 32, CC / 32);
    dim3 tblk(32, 8);
    transpose_kernel<<<tgrid, tblk>>>(f);

    wt_pack_kernel<<<(KK * 32 * OCC + 255) / 256, 256>>>(conv_w);

    offset_kernel<<<BB * WW, 128>>>(f, offset_w, offset_b, bn_gamma, bn_beta,
                                    bn_mean, bn_var);

    main_kernel<<<BB * WW, 256, main_smem>>>(conv_b, out);

    gn_kernel<<<(BB * OCC * WW * HH / 4) / 256, 256>>>(out, gn_gamma, gn_beta);
}

// round 10
// speedup vs baseline: 2.4606x; 1.2146x over previous
#include <cuda_runtime.h>
#include <cuda_fp16.h>
#include <math.h>

#define BB 4
#define CC 64
#define WW 128
#define HH 128
#define KK 9
#define OCC 64
#define GG 16
#define EPSV 1e-5f

// Scratch (static device globals — no allocation allowed)
__device__ __align__(16) float g_fT[BB * WW * HH * CC];    // NHWC
__device__ __align__(16) unsigned int g_Wt2[KK * 32 * OCC]; // [k][c2][oc] half2 (c pairs)
__device__ __align__(16) int4   g_pidx[BB * KK * WW * HH]; // 4 corner base indices
__device__ __align__(16) float4 g_pwgt[BB * KK * WW * HH]; // 4 bilinear weights
__device__ float g_stats[BB * GG * 2];                     // (sum, sumsq)

// ---------------------------------------------------------------------------
// Kernel 0: NCHW -> NHWC transpose of f
// ---------------------------------------------------------------------------
__global__ void transpose_kernel(const float* __restrict__ f) {
    __shared__ float tile[32][33];
    const int by = blockIdx.x;
    const int b = by >> 7, y = by & 127;
    const int x0 = blockIdx.y * 32;
    const int c0 = blockIdx.z * 32;
    #pragma unroll
    for (int i = threadIdx.y; i < 32; i += 8) {
        tile[i][threadIdx.x] = f[((b * CC + c0 + i) * WW + y) * HH + x0 + threadIdx.x];
    }
    __syncthreads();
    #pragma unroll
    for (int i = threadIdx.y; i < 32; i += 8) {
        g_fT[((b * WW + y) * HH + x0 + i) * CC + c0 + threadIdx.x] = tile[threadIdx.x][i];
    }
}

// ---------------------------------------------------------------------------
// Kernel W: conv_w [oc][c][k] -> g_Wt2 [k][c2][oc] as half2 (c even = low).
// Also zeroes the GN stat accumulators (block 0).
// ---------------------------------------------------------------------------
__global__ void wt_pack_kernel(const float* __restrict__ conv_w) {
    int i = blockIdx.x * 256 + threadIdx.x;   // over 9*32*64 = 18432
    if (i < KK * 32 * OCC) {
        int k = i / 2048;
        int r = i & 2047;
        int c2 = r >> 6, oc = r & 63;
        float w0 = conv_w[(((oc << 6) + (c2 << 1)) * KK) + k];
        float w1 = conv_w[(((oc << 6) + (c2 << 1) + 1) * KK) + k];
        __half2 p = __floats2half2_rn(w0, w1);
        g_Wt2[i] = *(unsigned int*)&p;
    }
    if (blockIdx.x == 0 && threadIdx.x < BB * GG * 2) g_stats[threadIdx.x] = 0.f;
}

// ---------------------------------------------------------------------------
// Kernel A: offset conv (9 of 18 oc) + BN + tanh + partial cumsum ->
// bilinear corner indices + weights. grid (B*W), block 128.
// ---------------------------------------------------------------------------
__global__ void __launch_bounds__(128) offset_kernel(
    const float* __restrict__ f, const float* __restrict__ offset_w,
    const float* __restrict__ offset_b, const float* __restrict__ bn_gamma,
    const float* __restrict__ bn_beta, const float* __restrict__ bn_mean,
    const float* __restrict__ bn_var) {
    __shared__ float w_s[64 * 108];
    __shared__ float rows[3][8][128];

    const int bw = blockIdx.x;
    const int b = bw >> 7, w = bw & 127;
    const int h = threadIdx.x;

    for (int i = h; i < 9 * 64 * 9; i += 128) {
        int k = i / 576;
        int r = i - k * 576;
        int c = r / 9, tap = r - (r / 9) * 9;
        w_s[c * 108 + tap * 12 + k] = offset_w[(k * 64 + c) * 9 + tap];
    }

    float acc[9];
    #pragma unroll
    for (int k = 0; k < 9; k++) acc[k] = 0.f;

    for (int cc = 0; cc < 64; cc += 8) {
        __syncthreads();
        for (int i = h; i < 3 * 8 * 128; i += 128) {
            int dy = i / 1024;
            int rem = i - dy * 1024;
            int c = rem >> 7, hh = rem & 127;
            int wr = w + dy - 1;
            float v = 0.f;
            if (wr >= 0 && wr < WW) v = f[((b * CC + cc + c) * WW + wr) * HH + hh];
            rows[dy][c][hh] = v;
        }
        __syncthreads();
        #pragma unroll
        for (int c = 0; c < 8; c++) {
            const float* wb = &w_s[(cc + c) * 108];
            #pragma unroll
            for (int dy = 0; dy < 3; dy++) {
                float vm = (h > 0) ? rows[dy][c][h - 1] : 0.f;
                float vc = rows[dy][c][h];
                float vp = (h < 127) ? rows[dy][c][h + 1] : 0.f;
                #pragma unroll
                for (int dx = 0; dx < 3; dx++) {
                    float v = (dx == 0) ? vm : ((dx == 1) ? vc : vp);
                    const float* wp = wb + (dy * 3 + dx) * 12;
                    float4 w0 = *(const float4*)(wp);
                    float4 w1 = *(const float4*)(wp + 4);
                    float w8 = wp[8];
                    acc[0] = fmaf(v, w0.x, acc[0]);
                    acc[1] = fmaf(v, w0.y, acc[1]);
                    acc[2] = fmaf(v, w0.z, acc[2]);
                    acc[3] = fmaf(v, w0.w, acc[3]);
                    acc[4] = fmaf(v, w1.x, acc[4]);
                    acc[5] = fmaf(v, w1.y, acc[5]);
                    acc[6] = fmaf(v, w1.z, acc[6]);
                    acc[7] = fmaf(v, w1.w, acc[7]);
                    acc[8] = fmaf(v, w8, acc[8]);
                }
            }
        }
    }

    float off[9];
    #pragma unroll
    for (int k = 0; k < 9; k++) {
        float sc = bn_gamma[k] * rsqrtf(bn_var[k] + EPSV);
        off[k] = tanhf((acc[k] + offset_b[k] - bn_mean[k]) * sc + bn_beta[k]);
    }
    float cum[9];
    cum[4] = 0.f;
    cum[0] = off[0];
    cum[8] = off[8];
    cum[5] = off[5];
    cum[6] = cum[5] + off[6];
    cum[7] = cum[6] + off[7];
    cum[3] = off[3];
    cum[2] = cum[3] + off[2];
    cum[1] = cum[2] + off[1];

    #pragma unroll
    for (int k = 0; k < 9; k++) {
        float ys = (float)w + cum[k];
        float xs = (float)h + (-5.0f + 1.125f * (float)k);   // linspace(-5,4,9)
        int y0 = (int)floorf(ys);
        y0 = max(0, min(y0, WW - 1));
        int y1 = min(y0 + 1, WW - 1);
        int x0 = (int)floorf(xs);
        x0 = max(0, min(x0, HH - 1));
        int x1 = min(x0 + 1, HH - 1);
        float wy1 = (float)y1 - ys;
        float wy0 = ys - (float)y0;
        float wx1 = (float)x1 - xs;
        float wx0 = xs - (float)x0;
        int4 ip;
        ip.x = ((b * WW + y0) * HH + x0) << 6;
        ip.y = ((b * WW + y0) * HH + x1) << 6;
        ip.z = ((b * WW + y1) * HH + x0) << 6;
        ip.w = ((b * WW + y1) * HH + x1) << 6;
        float4 wp;
        wp.x = wy1 * wx1;
        wp.y = wy1 * wx0;
        wp.z = wy0 * wx1;
        wp.w = wy0 * wx0;
        const int pidx = ((b * KK + k) * WW + w) * HH + h;
        g_pidx[pidx] = ip;
        g_pwgt[pidx] = wp;
    }
}

// ---------------------------------------------------------------------------
// Kernel B: bilinear gather + FP16 tensor-core GEMM + GN partial sums.
// grid (B*W), block 256 (8 warps), occ 4 -> single wave (592 slots >= 512).
// DOUBLE-BUFFERED wt2/dks by k parity -> ONE __syncthreads per k:
// gather(k+1) writes buf[(k+1)&1] while laggard warps read buf[k&1] in
// MMA(k); the sync bounds warp skew to one phase, so no WAR race.
// smem bytes: [0,9216) wt2_0 | [9216,18432) wt2_1 |
//             [18432,36864) dks_0 | [36864,55296) dks_1
// epilogue zbuf (64*132 floats) aliases the front, after a sync.
// ---------------------------------------------------------------------------
#define WTP2 72
#define DKPH 72
#define ZBP 132

__global__ void __launch_bounds__(256, 4) main_kernel(
    const float* __restrict__ conv_b, float* __restrict__ out) {
    extern __shared__ char smc[];
    float* zbuf = (float*)smc;                         // epilogue: 64*132 floats

    const int bw = blockIdx.x;
    const int b = bw >> 7, w = bw & 127;
    const int tid = threadIdx.x;
    const int lane = tid & 31;
    const int wid = tid >> 5;
    const int g = lane >> 2, t = lane & 3;
    const int h0 = (wid & 3) << 5;        // m32 tile
    const int n0 = (wid >> 2) << 5;       // n32 tile

    float acc[2][4][4];
    #pragma unroll
    for (int mi = 0; mi < 2; mi++)
        #pragma unroll
        for (int nj = 0; nj < 4; nj++)
            #pragma unroll
            for (int j = 0; j < 4; j++) acc[mi][nj][j] = 0.f;

    const int cq4 = (tid & 15) << 2;

    for (int k = 0; k < KK; k++) {
        const int par = k & 1;
        unsigned int* wt2 = (unsigned int*)(smc + par * 9216);
        unsigned short* dksh = (unsigned short*)(smc + 18432 + par * 18432);
        unsigned int* dku = (unsigned int*)dksh;       // row pitch 36 uints

        // stage weights: exactly 512 uint4s from g_Wt2[k]
        #pragma unroll
        for (int j = 0; j < 2; j++) {
            int i4 = tid + (j << 8);                 // 0..511
            int c2 = i4 >> 4, oc4 = (i4 & 15) << 2;
            *(uint4*)&wt2[c2 * WTP2 + oc4] =
                ((const uint4*)g_Wt2)[(k << 9) + i4];
        }
        // gather -> dksh[h][c] fp16
        const int pbase = ((b * KK + k) * WW + w) * HH;
        #pragma unroll
        for (int pass = 0; pass < 8; pass++) {
            const int hg = (tid >> 4) + (pass << 4);
            const int4 ip = __ldg(&g_pidx[pbase + hg]);
            const float4 wp = __ldg(&g_pwgt[pbase + hg]);
            float4 v = *(const float4*)&g_fT[ip.x + cq4];
            float rx = v.x * wp.x, ry = v.y * wp.x, rz = v.z * wp.x, rw = v.w * wp.x;
            v = *(const float4*)&g_fT[ip.y + cq4];
            rx = fmaf(v.x, wp.y, rx); ry = fmaf(v.y, wp.y, ry);
            rz = fmaf(v.z, wp.y, rz); rw = fmaf(v.w, wp.y, rw);
            v = *(const float4*)&g_fT[ip.z + cq4];
            rx = fmaf(v.x, wp.z, rx); ry = fmaf(v.y, wp.z, ry);
            rz = fmaf(v.z, wp.z, rz); rw = fmaf(v.w, wp.z, rw);
            v = *(const float4*)&g_fT[ip.w + cq4];
            rx = fmaf(v.x, wp.w, rx); ry = fmaf(v.y, wp.w, ry);
            rz = fmaf(v.z, wp.w, rz); rw = fmaf(v.w, wp.w, rw);
            __half2 p0 = __floats2half2_rn(rx, ry);   // low = even c
            __half2 p1 = __floats2half2_rn(rz, rw);
            uint2 pk;
            pk.x = *(unsigned int*)&p0;
            pk.y = *(unsigned int*)&p1;
            *(uint2*)&dksh[hg * DKPH + cq4] = pk;
        }
        __syncthreads();
        // MMA: warp tile m32 x n32, K=64 halves in 4 k16 chunks
        #pragma unroll
        for (int kc = 0; kc < 4; kc++) {
            const int ka = kc << 3;               // uint offset in dks row
            unsigned int a[2][4];
            #pragma unroll
            for (int mi = 0; mi < 2; mi++) {
                const int hb = h0 + (mi << 4);
                a[mi][0] = dku[(hb + g) * 36 + ka + t];
                a[mi][1] = dku[(hb + g + 8) * 36 + ka + t];
                a[mi][2] = dku[(hb + g) * 36 + ka + t + 4];
                a[mi][3] = dku[(hb + g + 8) * 36 + ka + t + 4];
            }
            #pragma unroll
            for (int nj = 0; nj < 4; nj++) {
                const int ncol = n0 + (nj << 3) + g;
                unsigned int b0 = wt2[(ka + t) * WTP2 + ncol];
                unsigned int b1 = wt2[(ka + t + 4) * WTP2 + ncol];
                #pragma unroll
                for (int mi = 0; mi < 2; mi++) {
                    asm("mma.sync.aligned.m16n8k16.row.col.f32.f16.f16.f32 "
                        "{%0,%1,%2,%3}, {%4,%5,%6,%7}, {%8,%9}, {%0,%1,%2,%3};"
                        : "+f"(acc[mi][nj][0]), "+f"(acc[mi][nj][1]),
                          "+f"(acc[mi][nj][2]), "+f"(acc[mi][nj][3])
                        : "r"(a[mi][0]), "r"(a[mi][1]), "r"(a[mi][2]), "r"(a[mi][3]),
                          "r"(b0), "r"(b1));
                }
            }
        }
    }

    // epilogue: fragments -> zbuf[oc][h] -> coalesced out + GN stats
    __syncthreads();     // all MMA reads of dks/wt2 done before aliasing as zbuf
    #pragma unroll
    for (int mi = 0; mi < 2; mi++) {
        #pragma unroll
        for (int nj = 0; nj < 4; nj++) {
            const int oc = n0 + (nj << 3) + (t << 1);
            const int hh = h0 + (mi << 4) + g;
            zbuf[oc * ZBP + hh] = acc[mi][nj][0];
            zbuf[(oc + 1) * ZBP + hh] = acc[mi][nj][1];
            zbuf[oc * ZBP + hh + 8] = acc[mi][nj][2];
            zbuf[(oc + 1) * ZBP + hh + 8] = acc[mi][nj][3];
        }
    }
    __syncthreads();
    const int oc = tid >> 2;
    const int hq = (tid & 3) << 5;
    const float bias = conv_b[oc];
    float s1 = 0.f, s2 = 0.f;
    float* op = out + ((b * OCC + oc) * WW + w) * HH + hq;
    #pragma unroll
    for (int j = 0; j < 8; j++) {
        float4 v = *(float4*)&zbuf[oc * ZBP + hq + (j << 2)];
        v.x += bias; v.y += bias; v.z += bias; v.w += bias;
        s1 += v.x + v.y + v.z + v.w;
        s2 += v.x * v.x + v.y * v.y + v.z * v.z + v.w * v.w;
        *(float4*)&op[j << 2] = v;
    }
    #pragma unroll
    for (int m = 1; m <= 8; m <<= 1) {
        s1 += __shfl_xor_sync(0xffffffffu, s1, m);
        s2 += __shfl_xor_sync(0xffffffffu, s2, m);
    }
    if ((lane & 15) == 0) {
        const int grp = oc >> 2;
        atomicAdd(&g_stats[(b * GG + grp) * 2 + 0], s1);
        atomicAdd(&g_stats[(b * GG + grp) * 2 + 1], s2);
    }
}

// ---------------------------------------------------------------------------
// Kernel C: GroupNorm finalize + ReLU (in place on out)
// ---------------------------------------------------------------------------
__global__ void __launch_bounds__(256) gn_kernel(float* __restrict__ out,
                                                 const float* __restrict__ gn_gamma,
                                                 const float* __restrict__ gn_beta) {
    const int idx = blockIdx.x * 256 + threadIdx.x;
    const int i4 = idx << 2;
    const int oc = (i4 >> 14) & 63;
    const int b = i4 >> 20;
    const int g = oc >> 2;
    const float inv = 1.0f / 65536.0f;
    float s1 = g_stats[(b * GG + g) * 2 + 0];
    float s2 = g_stats[(b * GG + g) * 2 + 1];
    float mean = s1 * inv;
    float var = s2 * inv - mean * mean;
    float sc = gn_gamma[oc] * rsqrtf(var + EPSV);
    float sh = gn_beta[oc] - mean * sc;
    float4* o4 = (float4*)out;
    float4 v = o4[idx];
    v.x = fmaxf(v.x * sc + sh, 0.f);
    v.y = fmaxf(v.y * sc + sh, 0.f);
    v.z = fmaxf(v.z * sc + sh, 0.f);
    v.w = fmaxf(v.w * sc + sh, 0.f);
    o4[idx] = v;
}

// ---------------------------------------------------------------------------
extern "C" void kernel_launch(void* const* d_in, const int* in_sizes, int n_in,
                              void* d_out, int out_size) {
    const float* f        = (const float*)d_in[0];
    const float* offset_w = (const float*)d_in[1];
    const float* offset_b = (const float*)d_in[2];
    const float* bn_gamma = (const float*)d_in[3];
    const float* bn_beta  = (const float*)d_in[4];
    const float* bn_mean  = (const float*)d_in[5];
    const float* bn_var   = (const float*)d_in[6];
    const float* conv_w   = (const float*)d_in[7];
    const float* conv_b   = (const float*)d_in[8];
    const float* gn_gamma = (const float*)d_in[9];
    const float* gn_beta  = (const float*)d_in[10];
    float* out = (float*)d_out;

    const int main_smem = 55296;   // 2x wt2 (9216) + 2x dks (18432)
    cudaFuncSetAttribute(main_kernel, cudaFuncAttributeMaxDynamicSharedMemorySize,
                         main_smem);

    dim3 tgrid(BB * WW, HH / 32, CC / 32);
    dim3 tblk(32, 8);
    transpose_kernel<<<tgrid, tblk>>>(f);

    wt_pack_kernel<<<(KK * 32 * OCC + 255) / 256, 256>>>(conv_w);

    offset_kernel<<<BB * WW, 128>>>(f, offset_w, offset_b, bn_gamma, bn_beta,
                                    bn_mean, bn_var);

    main_kernel<<<BB * WW, 256, main_smem>>>(conv_b, out);

    gn_kernel<<<(BB * OCC * WW * HH / 4) / 256, 256>>>(out, gn_gamma, gn_beta);
}

// round 12
// speedup vs baseline: 2.9725x; 1.2080x over previous
#include <cuda_runtime.h>
#include <cuda_fp16.h>
#include <math.h>

#define BB 4
#define CC 64
#define WW 128
#define HH 128
#define KK 9
#define OCC 64
#define GG 16
#define EPSV 1e-5f

// Scratch (static device globals — no allocation allowed)
__device__ __align__(16) unsigned short g_fTh[BB * WW * HH * CC]; // NHWC fp16
__device__ __align__(16) unsigned int g_Wt2[KK * 32 * OCC]; // [k][c2][oc] half2
__device__ __align__(16) uint4 g_par[BB * KK * WW * HH];    // {base, dx|dy<<16, w01, w23}
__device__ float g_stats[BB * GG * 2];                      // (sum, sumsq)

// ---------------------------------------------------------------------------
// Kernel W: conv_w [oc][c][k] -> g_Wt2 [k][c2][oc] as half2 (c even = low).
// Also zeroes the GN stat accumulators (block 0).
// ---------------------------------------------------------------------------
__global__ void wt_pack_kernel(const float* __restrict__ conv_w) {
    int i = blockIdx.x * 256 + threadIdx.x;   // over 9*32*64 = 18432
    if (i < KK * 32 * OCC) {
        int k = i / 2048;
        int r = i & 2047;
        int c2 = r >> 6, oc = r & 63;
        float w0 = conv_w[(((oc << 6) + (c2 << 1)) * KK) + k];
        float w1 = conv_w[(((oc << 6) + (c2 << 1) + 1) * KK) + k];
        __half2 p = __floats2half2_rn(w0, w1);
        g_Wt2[i] = *(unsigned int*)&p;
    }
    if (blockIdx.x == 0 && threadIdx.x < BB * GG * 2) g_stats[threadIdx.x] = 0.f;
}

// ---------------------------------------------------------------------------
// Kernel A: offset conv (9 of 18 oc) + BN + tanh + partial cumsum ->
// packed bilinear params; ALSO writes fp16 NHWC copy of f row w (fused
// transpose — rows[1] holds exactly f[b, :, w, :]). grid (B*W), block 128.
// ---------------------------------------------------------------------------
__global__ void __launch_bounds__(128) offset_kernel(
    const float* __restrict__ f, const float* __restrict__ offset_w,
    const float* __restrict__ offset_b, const float* __restrict__ bn_gamma,
    const float* __restrict__ bn_beta, const float* __restrict__ bn_mean,
    const float* __restrict__ bn_var) {
    __shared__ float w_s[64 * 108];
    __shared__ float rows[3][8][128];

    const int bw = blockIdx.x;
    const int b = bw >> 7, w = bw & 127;
    const int h = threadIdx.x;

    for (int i = h; i < 9 * 64 * 9; i += 128) {
        int k = i / 576;
        int r = i - k * 576;
        int c = r / 9, tap = r - (r / 9) * 9;
        w_s[c * 108 + tap * 12 + k] = offset_w[(k * 64 + c) * 9 + tap];
    }

    float acc[9];
    #pragma unroll
    for (int k = 0; k < 9; k++) acc[k] = 0.f;

    for (int cc = 0; cc < 64; cc += 8) {
        __syncthreads();
        for (int i = h; i < 3 * 8 * 128; i += 128) {
            int dy = i / 1024;
            int rem = i - dy * 1024;
            int c = rem >> 7, hh = rem & 127;
            int wr = w + dy - 1;
            float v = 0.f;
            if (wr >= 0 && wr < WW) v = f[((b * CC + cc + c) * WW + wr) * HH + hh];
            rows[dy][c][hh] = v;
        }
        __syncthreads();
        // fused transpose: write fp16 NHWC row w for this 8-channel chunk
        {
            __half2 hp[4];
            #pragma unroll
            for (int c2 = 0; c2 < 4; c2++)
                hp[c2] = __floats2half2_rn(rows[1][2 * c2][h], rows[1][2 * c2 + 1][h]);
            *(uint4*)&g_fTh[((b * WW + w) * HH + h) * 64 + cc] = *(uint4*)hp;
        }
        #pragma unroll
        for (int c = 0; c < 8; c++) {
            const float* wb = &w_s[(cc + c) * 108];
            #pragma unroll
            for (int dy = 0; dy < 3; dy++) {
                float vm = (h > 0) ? rows[dy][c][h - 1] : 0.f;
                float vc = rows[dy][c][h];
                float vp = (h < 127) ? rows[dy][c][h + 1] : 0.f;
                #pragma unroll
                for (int dx = 0; dx < 3; dx++) {
                    float v = (dx == 0) ? vm : ((dx == 1) ? vc : vp);
                    const float* wp = wb + (dy * 3 + dx) * 12;
                    float4 w0 = *(const float4*)(wp);
                    float4 w1 = *(const float4*)(wp + 4);
                    float w8 = wp[8];
                    acc[0] = fmaf(v, w0.x, acc[0]);
                    acc[1] = fmaf(v, w0.y, acc[1]);
                    acc[2] = fmaf(v, w0.z, acc[2]);
                    acc[3] = fmaf(v, w0.w, acc[3]);
                    acc[4] = fmaf(v, w1.x, acc[4]);
                    acc[5] = fmaf(v, w1.y, acc[5]);
                    acc[6] = fmaf(v, w1.z, acc[6]);
                    acc[7] = fmaf(v, w1.w, acc[7]);
                    acc[8] = fmaf(v, w8, acc[8]);
                }
            }
        }
    }

    float off[9];
    #pragma unroll
    for (int k = 0; k < 9; k++) {
        float sc = bn_gamma[k] * rsqrtf(bn_var[k] + EPSV);
        off[k] = tanhf((acc[k] + offset_b[k] - bn_mean[k]) * sc + bn_beta[k]);
    }
    float cum[9];
    cum[4] = 0.f;
    cum[0] = off[0];
    cum[8] = off[8];
    cum[5] = off[5];
    cum[6] = cum[5] + off[6];
    cum[7] = cum[6] + off[7];
    cum[3] = off[3];
    cum[2] = cum[3] + off[2];
    cum[1] = cum[2] + off[1];

    #pragma unroll
    for (int k = 0; k < 9; k++) {
        float ys = (float)w + cum[k];
        float xs = (float)h + (-5.0f + 1.125f * (float)k);   // linspace(-5,4,9)
        int y0 = (int)floorf(ys);
        y0 = max(0, min(y0, WW - 1));
        int y1 = min(y0 + 1, WW - 1);
        int x0 = (int)floorf(xs);
        x0 = max(0, min(x0, HH - 1));
        int x1 = min(x0 + 1, HH - 1);
        float wy1 = (float)y1 - ys;
        float wy0 = ys - (float)y0;
        float wx1 = (float)x1 - xs;
        float wx0 = xs - (float)x0;
        uint4 pr;
        pr.x = (unsigned int)(((b * WW + y0) * HH + x0) << 6);   // base (halves)
        pr.y = (unsigned int)((x1 - x0) * 64) |
               ((unsigned int)((y1 - y0) * 8192) << 16);         // dx | dy<<16
        __half2 w01 = __floats2half2_rn(wy1 * wx1, wy1 * wx0);
        __half2 w23 = __floats2half2_rn(wy0 * wx1, wy0 * wx0);
        pr.z = *(unsigned int*)&w01;
        pr.w = *(unsigned int*)&w23;
        g_par[((b * KK + k) * WW + w) * HH + h] = pr;
    }
}

// ---------------------------------------------------------------------------
// Kernel B: bilinear gather (fp16 source, fp32 interp) + FP16 tensor-core
// GEMM + GN partial sums. grid (B*W), block 256 (8 warps), occ 4.
// Double-buffered wt2/dks by k parity -> one __syncthreads per k.
// smem bytes: [0,9216) wt2_0 | [9216,18432) wt2_1 |
//             [18432,36864) dks_0 | [36864,55296) dks_1
// epilogue zbuf (64*132 floats) aliases the front, after a sync.
// ---------------------------------------------------------------------------
#define WTP2 72
#define DKPH 72
#define ZBP 132

__global__ void __launch_bounds__(256, 4) main_kernel(
    const float* __restrict__ conv_b, float* __restrict__ out) {
    extern __shared__ char smc[];
    float* zbuf = (float*)smc;                         // epilogue: 64*132 floats

    const int bw = blockIdx.x;
    const int b = bw >> 7, w = bw & 127;
    const int tid = threadIdx.x;
    const int lane = tid & 31;
    const int wid = tid >> 5;
    const int g = lane >> 2, t = lane & 3;
    const int h0 = (wid & 3) << 5;        // m32 tile
    const int n0 = (wid >> 2) << 5;       // n32 tile

    float acc[2][4][4];
    #pragma unroll
    for (int mi = 0; mi < 2; mi++)
        #pragma unroll
        for (int nj = 0; nj < 4; nj++)
            #pragma unroll
            for (int j = 0; j < 4; j++) acc[mi][nj][j] = 0.f;

    const int cq4 = (tid & 15) << 2;       // channel offset in halves (4 ch)

    for (int k = 0; k < KK; k++) {
        const int par = k & 1;
        unsigned int* wt2 = (unsigned int*)(smc + par * 9216);
        unsigned short* dksh = (unsigned short*)(smc + 18432 + par * 18432);
        unsigned int* dku = (unsigned int*)dksh;       // row pitch 36 uints

        // stage weights: exactly 512 uint4s from g_Wt2[k]
        #pragma unroll
        for (int j = 0; j < 2; j++) {
            int i4 = tid + (j << 8);                 // 0..511
            int c2 = i4 >> 4, oc4 = (i4 & 15) << 2;
            *(uint4*)&wt2[c2 * WTP2 + oc4] =
                ((const uint4*)g_Wt2)[(k << 9) + i4];
        }
        // gather -> dksh[h][c] fp16 (fp32 interpolation)
        const int pbase = ((b * KK + k) * WW + w) * HH;
        #pragma unroll
        for (int pass = 0; pass < 8; pass++) {
            const int hg = (tid >> 4) + (pass << 4);
            const uint4 pr = __ldg(&g_par[pbase + hg]);
            const int base = (int)pr.x + cq4;
            const int dx = (int)(pr.y & 0xffffu);
            const int dy = (int)(pr.y >> 16);
            const __half2 hw01 = *(const __half2*)&pr.z;
            const __half2 hw23 = *(const __half2*)&pr.w;
            const float w00 = __low2float(hw01), w01f = __high2float(hw01);
            const float w10 = __low2float(hw23), w11f = __high2float(hw23);
            uint2 a00 = *(const uint2*)&g_fTh[base];
            uint2 a01 = *(const uint2*)&g_fTh[base + dx];
            uint2 a10 = *(const uint2*)&g_fTh[base + dy];
            uint2 a11 = *(const uint2*)&g_fTh[base + dx + dy];
            float2 u0 = __half22float2(*(__half2*)&a00.x);
            float2 u1 = __half22float2(*(__half2*)&a00.y);
            float rx = u0.x * w00, ry = u0.y * w00, rz = u1.x * w00, rw = u1.y * w00;
            u0 = __half22float2(*(__half2*)&a01.x);
            u1 = __half22float2(*(__half2*)&a01.y);
            rx = fmaf(u0.x, w01f, rx); ry = fmaf(u0.y, w01f, ry);
            rz = fmaf(u1.x, w01f, rz); rw = fmaf(u1.y, w01f, rw);
            u0 = __half22float2(*(__half2*)&a10.x);
            u1 = __half22float2(*(__half2*)&a10.y);
            rx = fmaf(u0.x, w10, rx); ry = fmaf(u0.y, w10, ry);
            rz = fmaf(u1.x, w10, rz); rw = fmaf(u1.y, w10, rw);
            u0 = __half22float2(*(__half2*)&a11.x);
            u1 = __half22float2(*(__half2*)&a11.y);
            rx = fmaf(u0.x, w11f, rx); ry = fmaf(u0.y, w11f, ry);
            rz = fmaf(u1.x, w11f, rz); rw = fmaf(u1.y, w11f, rw);
            __half2 p0 = __floats2half2_rn(rx, ry);   // low = even c
            __half2 p1 = __floats2half2_rn(rz, rw);
            uint2 pk;
            pk.x = *(unsigned int*)&p0;
            pk.y = *(unsigned int*)&p1;
            *(uint2*)&dksh[hg * DKPH + cq4] = pk;
        }
        __syncthreads();
        // MMA: warp tile m32 x n32, K=64 halves in 4 k16 chunks
        #pragma unroll
        for (int kc = 0; kc < 4; kc++) {
            const int ka = kc << 3;               // uint offset in dks row
            unsigned int a[2][4];
            #pragma unroll
            for (int mi = 0; mi < 2; mi++) {
                const int hb = h0 + (mi << 4);
                a[mi][0] = dku[(hb + g) * 36 + ka + t];
                a[mi][1] = dku[(hb + g + 8) * 36 + ka + t];
                a[mi][2] = dku[(hb + g) * 36 + ka + t + 4];
                a[mi][3] = dku[(hb + g + 8) * 36 + ka + t + 4];
            }
            #pragma unroll
            for (int nj = 0; nj < 4; nj++) {
                const int ncol = n0 + (nj << 3) + g;
                unsigned int b0 = wt2[(ka + t) * WTP2 + ncol];
                unsigned int b1 = wt2[(ka + t + 4) * WTP2 + ncol];
                #pragma unroll
                for (int mi = 0; mi < 2; mi++) {
                    asm("mma.sync.aligned.m16n8k16.row.col.f32.f16.f16.f32 "
                        "{%0,%1,%2,%3}, {%4,%5,%6,%7}, {%8,%9}, {%0,%1,%2,%3};"
                        : "+f"(acc[mi][nj][0]), "+f"(acc[mi][nj][1]),
                          "+f"(acc[mi][nj][2]), "+f"(acc[mi][nj][3])
                        : "r"(a[mi][0]), "r"(a[mi][1]), "r"(a[mi][2]), "r"(a[mi][3]),
                          "r"(b0), "r"(b1));
                }
            }
        }
    }

    // epilogue: fragments -> zbuf[oc][h] -> coalesced out + GN stats
    __syncthreads();     // all MMA reads of dks/wt2 done before aliasing as zbuf
    #pragma unroll
    for (int mi = 0; mi < 2; mi++) {
        #pragma unroll
        for (int nj = 0; nj < 4; nj++) {
            const int oc = n0 + (nj << 3) + (t << 1);
            const int hh = h0 + (mi << 4) + g;
            zbuf[oc * ZBP + hh] = acc[mi][nj][0];
            zbuf[(oc + 1) * ZBP + hh] = acc[mi][nj][1];
            zbuf[oc * ZBP + hh + 8] = acc[mi][nj][2];
            zbuf[(oc + 1) * ZBP + hh + 8] = acc[mi][nj][3];
        }
    }
    __syncthreads();
    const int oc = tid >> 2;
    const int hq = (tid & 3) << 5;
    const float bias = conv_b[oc];
    float s1 = 0.f, s2 = 0.f;
    float* op = out + ((b * OCC + oc) * WW + w) * HH + hq;
    #pragma unroll
    for (int j = 0; j < 8; j++) {
        float4 v = *(float4*)&zbuf[oc * ZBP + hq + (j << 2)];
        v.x += bias; v.y += bias; v.z += bias; v.w += bias;
        s1 += v.x + v.y + v.z + v.w;
        s2 += v.x * v.x + v.y * v.y + v.z * v.z + v.w * v.w;
        *(float4*)&op[j << 2] = v;
    }
    #pragma unroll
    for (int m = 1; m <= 8; m <<= 1) {
        s1 += __shfl_xor_sync(0xffffffffu, s1, m);
        s2 += __shfl_xor_sync(0xffffffffu, s2, m);
    }
    if ((lane & 15) == 0) {
        const int grp = oc >> 2;
        atomicAdd(&g_stats[(b * GG + grp) * 2 + 0], s1);
        atomicAdd(&g_stats[(b * GG + grp) * 2 + 1], s2);
    }
}

// ---------------------------------------------------------------------------
// Kernel C: GroupNorm finalize + ReLU (in place on out)
// ---------------------------------------------------------------------------
__global__ void __launch_bounds__(256) gn_kernel(float* __restrict__ out,
                                                 const float* __restrict__ gn_gamma,
                                                 const float* __restrict__ gn_beta) {
    const int idx = blockIdx.x * 256 + threadIdx.x;
    const int i4 = idx << 2;
    const int oc = (i4 >> 14) & 63;
    const int b = i4 >> 20;
    const int g = oc >> 2;
    const float inv = 1.0f / 65536.0f;
    float s1 = g_stats[(b * GG + g) * 2 + 0];
    float s2 = g_stats[(b * GG + g) * 2 + 1];
    float mean = s1 * inv;
    float var = s2 * inv - mean * mean;
    float sc = gn_gamma[oc] * rsqrtf(var + EPSV);
    float sh = gn_beta[oc] - mean * sc;
    float4* o4 = (float4*)out;
    float4 v = o4[idx];
    v.x = fmaxf(v.x * sc + sh, 0.f);
    v.y = fmaxf(v.y * sc + sh, 0.f);
    v.z = fmaxf(v.z * sc + sh, 0.f);
    v.w = fmaxf(v.w * sc + sh, 0.f);
    o4[idx] = v;
}

// ---------------------------------------------------------------------------
extern "C" void kernel_launch(void* const* d_in, const int* in_sizes, int n_in,
                              void* d_out, int out_size) {
    const float* f        = (const float*)d_in[0];
    const float* offset_w = (const float*)d_in[1];
    const float* offset_b = (const float*)d_in[2];
    const float* bn_gamma = (const float*)d_in[3];
    const float* bn_beta  = (const float*)d_in[4];
    const float* bn_mean  = (const float*)d_in[5];
    const float* bn_var   = (const float*)d_in[6];
    const float* conv_w   = (const float*)d_in[7];
    const float* conv_b   = (const float*)d_in[8];
    const float* gn_gamma = (const float*)d_in[9];
    const float* gn_beta  = (const float*)d_in[10];
    float* out = (float*)d_out;

    const int main_smem = 55296;   // 2x wt2 (9216) + 2x dks (18432)
    cudaFuncSetAttribute(main_kernel, cudaFuncAttributeMaxDynamicSharedMemorySize,
                         main_smem);

    wt_pack_kernel<<<(KK * 32 * OCC + 255) / 256, 256>>>(conv_w);

    offset_kernel<<<BB * WW, 128>>>(f, offset_w, offset_b, bn_gamma, bn_beta,
                                    bn_mean, bn_var);

    main_kernel<<<BB * WW, 256, main_smem>>>(conv_b, out);

    gn_kernel<<<(BB * OCC * WW * HH / 4) / 256, 256>>>(out, gn_gamma, gn_beta);
}

// round 13
// speedup vs baseline: 3.0859x; 1.0381x over previous
#include <cuda_runtime.h>
#include <cuda_fp16.h>
#include <math.h>

#define BB 4
#define CC 64
#define WW 128
#define HH 128
#define KK 9
#define OCC 64
#define GG 16
#define EPSV 1e-5f

// Scratch (static device globals — no allocation allowed)
__device__ __align__(16) unsigned short g_fTh[BB * WW * HH * CC]; // NHWC fp16
__device__ __align__(16) unsigned int g_Wt2[KK * CC * (OCC / 2)]; // [k][c][oc/2] uint (oc pairs)
__device__ __align__(16) uint4 g_par[BB * KK * WW * HH];    // {base, dx|dy<<16, w01, w23}
__device__ float g_stats[BB * GG * 2];                      // (sum, sumsq)

__device__ __forceinline__ unsigned int s2u(const void* p) {
    unsigned int a;
    asm("{ .reg .u64 t; cvta.to.shared.u64 t, %1; cvt.u32.u64 %0, t; }"
        : "=r"(a) : "l"(p));
    return a;
}

#define LDSM_X4(r0, r1, r2, r3, addr) \
    asm volatile("ldmatrix.sync.aligned.m8n8.x4.shared.b16 {%0,%1,%2,%3}, [%4];" \
                 : "=r"(r0), "=r"(r1), "=r"(r2), "=r"(r3) : "r"(addr))
#define LDSM_X4_T(r0, r1, r2, r3, addr) \
    asm volatile("ldmatrix.sync.aligned.m8n8.x4.trans.shared.b16 {%0,%1,%2,%3}, [%4];" \
                 : "=r"(r0), "=r"(r1), "=r"(r2), "=r"(r3) : "r"(addr))

// ---------------------------------------------------------------------------
// Kernel W: conv_w [oc][c][k] -> g_Wt2 [k][c][oc] halves (oc-paired uints).
// Also zeroes the GN stat accumulators (block 0).
// ---------------------------------------------------------------------------
__global__ void wt_pack_kernel(const float* __restrict__ conv_w) {
    int i = blockIdx.x * 256 + threadIdx.x;   // over 9*64*32 = 18432
    if (i < KK * CC * (OCC / 2)) {
        int k = i / 2048;
        int r = i & 2047;
        int c = r >> 5, oc2 = (r & 31) << 1;
        float w0 = conv_w[(((oc2 << 6) + c) * KK) + k];
        float w1 = conv_w[((((oc2 + 1) << 6) + c) * KK) + k];
        __half2 p = __floats2half2_rn(w0, w1);
        g_Wt2[i] = *(unsigned int*)&p;
    }
    if (blockIdx.x == 0 && threadIdx.x < BB * GG * 2) g_stats[threadIdx.x] = 0.f;
}

// ---------------------------------------------------------------------------
// Kernel A: offset conv (9 of 18 oc) + BN + tanh + partial cumsum ->
// packed bilinear params; ALSO writes fp16 NHWC copy of f row w (fused
// transpose — rows[1] holds exactly f[b, :, w, :]). grid (B*W), block 128.
// ---------------------------------------------------------------------------
__global__ void __launch_bounds__(128) offset_kernel(
    const float* __restrict__ f, const float* __restrict__ offset_w,
    const float* __restrict__ offset_b, const float* __restrict__ bn_gamma,
    const float* __restrict__ bn_beta, const float* __restrict__ bn_mean,
    const float* __restrict__ bn_var) {
    __shared__ float w_s[64 * 108];
    __shared__ float rows[3][8][128];

    const int bw = blockIdx.x;
    const int b = bw >> 7, w = bw & 127;
    const int h = threadIdx.x;

    for (int i = h; i < 9 * 64 * 9; i += 128) {
        int k = i / 576;
        int r = i - k * 576;
        int c = r / 9, tap = r - (r / 9) * 9;
        w_s[c * 108 + tap * 12 + k] = offset_w[(k * 64 + c) * 9 + tap];
    }

    float acc[9];
    #pragma unroll
    for (int k = 0; k < 9; k++) acc[k] = 0.f;

    for (int cc = 0; cc < 64; cc += 8) {
        __syncthreads();
        for (int i = h; i < 3 * 8 * 128; i += 128) {
            int dy = i / 1024;
            int rem = i - dy * 1024;
            int c = rem >> 7, hh = rem & 127;
            int wr = w + dy - 1;
            float v = 0.f;
            if (wr >= 0 && wr < WW) v = f[((b * CC + cc + c) * WW + wr) * HH + hh];
            rows[dy][c][hh] = v;
        }
        __syncthreads();
        // fused transpose: write fp16 NHWC row w for this 8-channel chunk
        {
            __half2 hp[4];
            #pragma unroll
            for (int c2 = 0; c2 < 4; c2++)
                hp[c2] = __floats2half2_rn(rows[1][2 * c2][h], rows[1][2 * c2 + 1][h]);
            *(uint4*)&g_fTh[((b * WW + w) * HH + h) * 64 + cc] = *(uint4*)hp;
        }
        #pragma unroll
        for (int c = 0; c < 8; c++) {
            const float* wb = &w_s[(cc + c) * 108];
            #pragma unroll
            for (int dy = 0; dy < 3; dy++) {
                float vm = (h > 0) ? rows[dy][c][h - 1] : 0.f;
                float vc = rows[dy][c][h];
                float vp = (h < 127) ? rows[dy][c][h + 1] : 0.f;
                #pragma unroll
                for (int dx = 0; dx < 3; dx++) {
                    float v = (dx == 0) ? vm : ((dx == 1) ? vc : vp);
                    const float* wp = wb + (dy * 3 + dx) * 12;
                    float4 w0 = *(const float4*)(wp);
                    float4 w1 = *(const float4*)(wp + 4);
                    float w8 = wp[8];
                    acc[0] = fmaf(v, w0.x, acc[0]);
                    acc[1] = fmaf(v, w0.y, acc[1]);
                    acc[2] = fmaf(v, w0.z, acc[2]);
                    acc[3] = fmaf(v, w0.w, acc[3]);
                    acc[4] = fmaf(v, w1.x, acc[4]);
                    acc[5] = fmaf(v, w1.y, acc[5]);
                    acc[6] = fmaf(v, w1.z, acc[6]);
                    acc[7] = fmaf(v, w1.w, acc[7]);
                    acc[8] = fmaf(v, w8, acc[8]);
                }
            }
        }
    }

    float off[9];
    #pragma unroll
    for (int k = 0; k < 9; k++) {
        float sc = bn_gamma[k] * rsqrtf(bn_var[k] + EPSV);
        off[k] = tanhf((acc[k] + offset_b[k] - bn_mean[k]) * sc + bn_beta[k]);
    }
    float cum[9];
    cum[4] = 0.f;
    cum[0] = off[0];
    cum[8] = off[8];
    cum[5] = off[5];
    cum[6] = cum[5] + off[6];
    cum[7] = cum[6] + off[7];
    cum[3] = off[3];
    cum[2] = cum[3] + off[2];
    cum[1] = cum[2] + off[1];

    #pragma unroll
    for (int k = 0; k < 9; k++) {
        float ys = (float)w + cum[k];
        float xs = (float)h + (-5.0f + 1.125f * (float)k);   // linspace(-5,4,9)
        int y0 = (int)floorf(ys);
        y0 = max(0, min(y0, WW - 1));
        int y1 = min(y0 + 1, WW - 1);
        int x0 = (int)floorf(xs);
        x0 = max(0, min(x0, HH - 1));
        int x1 = min(x0 + 1, HH - 1);
        float wy1 = (float)y1 - ys;
        float wy0 = ys - (float)y0;
        float wx1 = (float)x1 - xs;
        float wx0 = xs - (float)x0;
        uint4 pr;
        pr.x = (unsigned int)(((b * WW + y0) * HH + x0) << 6);   // base (halves)
        pr.y = (unsigned int)((x1 - x0) * 64) |
               ((unsigned int)((y1 - y0) * 8192) << 16);         // dx | dy<<16
        __half2 w01 = __floats2half2_rn(wy1 * wx1, wy1 * wx0);
        __half2 w23 = __floats2half2_rn(wy0 * wx1, wy0 * wx0);
        pr.z = *(unsigned int*)&w01;
        pr.w = *(unsigned int*)&w23;
        g_par[((b * KK + k) * WW + w) * HH + h] = pr;
    }
}

// ---------------------------------------------------------------------------
// Kernel B: bilinear gather (fp16 source, fp32 interp) + FP16 tensor-core
// GEMM (ldmatrix fragment loads) + GN partial sums.
// grid (B*W), block 256 (8 warps), occ 4, double-buffered by k parity.
// smem bytes: [0,9216) wtB_0 [k-rows c=64][oc] pitch 72 halves
//             [9216,18432) wtB_1
//             [18432,36864) dks_0 [h][c] pitch 72 halves | [36864,55296) dks_1
// epilogue zbuf (64*132 floats) aliases the front, after a sync.
// ---------------------------------------------------------------------------
#define DKPH 72
#define ZBP 132

__global__ void __launch_bounds__(256, 4) main_kernel(
    const float* __restrict__ conv_b, float* __restrict__ out) {
    extern __shared__ char smc[];
    float* zbuf = (float*)smc;                         // epilogue: 64*132 floats

    const int bw = blockIdx.x;
    const int b = bw >> 7, w = bw & 127;
    const int tid = threadIdx.x;
    const int lane = tid & 31;
    const int wid = tid >> 5;
    const int g = lane >> 2, t = lane & 3;
    const int h0 = (wid & 3) << 5;        // m32 tile
    const int n0 = (wid >> 2) << 5;       // n32 tile

    const unsigned int smem_u32 = s2u(smc);

    // ldmatrix per-lane address offsets (bytes); mat = lane>>3
    const int mat = lane >> 3;
    const int mrow = ((mat & 1) << 3) | (lane & 7);
    const int mcol = (mat >> 1) << 3;                  // halves
    const int aoff = (h0 + mrow) * 144 + mcol * 2;     // A: dks rows
    const int boff = mrow * 144 + (n0 + mcol) * 2;     // B: wt k-rows

    float acc[2][4][4];
    #pragma unroll
    for (int mi = 0; mi < 2; mi++)
        #pragma unroll
        for (int nj = 0; nj < 4; nj++)
            #pragma unroll
            for (int j = 0; j < 4; j++) acc[mi][nj][j] = 0.f;

    const int cq4 = (tid & 15) << 2;       // channel offset in halves (4 ch)

    for (int k = 0; k < KK; k++) {
        const int par = k & 1;
        unsigned int* wt2 = (unsigned int*)(smc + par * 9216);
        unsigned short* dksh = (unsigned short*)(smc + 18432 + par * 18432);
        const unsigned int wt32 = smem_u32 + par * 9216;
        const unsigned int dk32 = smem_u32 + 18432 + par * 18432;

        // stage weights: exactly 512 uint4s; dst row pitch 9 uint4 (144 B)
        #pragma unroll
        for (int j = 0; j < 2; j++) {
            int i4 = tid + (j << 8);                 // 0..511
            int row = i4 >> 3, col = i4 & 7;
            *((uint4*)wt2 + row * 9 + col) = ((const uint4*)g_Wt2)[(k << 9) + i4];
        }
        // gather -> dksh[h][c] fp16 (fp32 interpolation)
        const int pbase = ((b * KK + k) * WW + w) * HH;
        #pragma unroll
        for (int pass = 0; pass < 8; pass++) {
            const int hg = (tid >> 4) + (pass << 4);
            const uint4 pr = __ldg(&g_par[pbase + hg]);
            const int base = (int)pr.x + cq4;
            const int dx = (int)(pr.y & 0xffffu);
            const int dy = (int)(pr.y >> 16);
            const __half2 hw01 = *(const __half2*)&pr.z;
            const __half2 hw23 = *(const __half2*)&pr.w;
            const float w00 = __low2float(hw01), w01f = __high2float(hw01);
            const float w10 = __low2float(hw23), w11f = __high2float(hw23);
            uint2 a00 = *(const uint2*)&g_fTh[base];
            uint2 a01 = *(const uint2*)&g_fTh[base + dx];
            uint2 a10 = *(const uint2*)&g_fTh[base + dy];
            uint2 a11 = *(const uint2*)&g_fTh[base + dx + dy];
            float2 u0 = __half22float2(*(__half2*)&a00.x);
            float2 u1 = __half22float2(*(__half2*)&a00.y);
            float rx = u0.x * w00, ry = u0.y * w00, rz = u1.x * w00, rw = u1.y * w00;
            u0 = __half22float2(*(__half2*)&a01.x);
            u1 = __half22float2(*(__half2*)&a01.y);
            rx = fmaf(u0.x, w01f, rx); ry = fmaf(u0.y, w01f, ry);
            rz = fmaf(u1.x, w01f, rz); rw = fmaf(u1.y, w01f, rw);
            u0 = __half22float2(*(__half2*)&a10.x);
            u1 = __half22float2(*(__half2*)&a10.y);
            rx = fmaf(u0.x, w10, rx); ry = fmaf(u0.y, w10, ry);
            rz = fmaf(u1.x, w10, rz); rw = fmaf(u1.y, w10, rw);
            u0 = __half22float2(*(__half2*)&a11.x);
            u1 = __half22float2(*(__half2*)&a11.y);
            rx = fmaf(u0.x, w11f, rx); ry = fmaf(u0.y, w11f, ry);
            rz = fmaf(u1.x, w11f, rz); rw = fmaf(u1.y, w11f, rw);
            __half2 p0 = __floats2half2_rn(rx, ry);   // low = even c
            __half2 p1 = __floats2half2_rn(rz, rw);
            uint2 pk;
            pk.x = *(unsigned int*)&p0;
            pk.y = *(unsigned int*)&p1;
            *(uint2*)&dksh[hg * DKPH + cq4] = pk;
        }
        __syncthreads();
        // MMA: warp tile m32 x n32, K=64 halves in 4 k16 chunks, ldmatrix frags
        #pragma unroll
        for (int kc = 0; kc < 4; kc++) {
            unsigned int a0[4], a1[4], bb0[4], bb1[4];
            const unsigned int aa = dk32 + aoff + kc * 32;
            LDSM_X4(a0[0], a0[1], a0[2], a0[3], aa);
            LDSM_X4(a1[0], a1[1], a1[2], a1[3], aa + 16 * 144);
            const unsigned int ba = wt32 + boff + kc * 2304;   // 16 k-rows
            LDSM_X4_T(bb0[0], bb0[1], bb0[2], bb0[3], ba);
            LDSM_X4_T(bb1[0], bb1[1], bb1[2], bb1[3], ba + 32);
            #pragma unroll
            for (int nj = 0; nj < 4; nj++) {
                const unsigned int b0 = (nj < 2) ? bb0[(nj & 1) << 1] : bb1[(nj & 1) << 1];
                const unsigned int b1 = (nj < 2) ? bb0[((nj & 1) << 1) + 1]
                                                 : bb1[((nj & 1) << 1) + 1];
                #pragma unroll
                for (int mi = 0; mi < 2; mi++) {
                    unsigned int* a = mi ? a1 : a0;
                    asm("mma.sync.aligned.m16n8k16.row.col.f32.f16.f16.f32 "
                        "{%0,%1,%2,%3}, {%4,%5,%6,%7}, {%8,%9}, {%0,%1,%2,%3};"
                        : "+f"(acc[mi][nj][0]), "+f"(acc[mi][nj][1]),
                          "+f"(acc[mi][nj][2]), "+f"(acc[mi][nj][3])
                        : "r"(a[0]), "r"(a[1]), "r"(a[2]), "r"(a[3]),
                          "r"(b0), "r"(b1));
                }
            }
        }
    }

    // epilogue: fragments -> zbuf[oc][h] -> coalesced out + GN stats
    __syncthreads();     // all MMA reads of dks/wt2 done before aliasing as zbuf
    #pragma unroll
    for (int mi = 0; mi < 2; mi++) {
        #pragma unroll
        for (int nj = 0; nj < 4; nj++) {
            const int oc = n0 + (nj << 3) + (t << 1);
            const int hh = h0 + (mi << 4) + g;
            zbuf[oc * ZBP + hh] = acc[mi][nj][0];
            zbuf[(oc + 1) * ZBP + hh] = acc[mi][nj][1];
            zbuf[oc * ZBP + hh + 8] = acc[mi][nj][2];
            zbuf[(oc + 1) * ZBP + hh + 8] = acc[mi][nj][3];
        }
    }
    __syncthreads();
    const int oc = tid >> 2;
    const int hq = (tid & 3) << 5;
    const float bias = conv_b[oc];
    float s1 = 0.f, s2 = 0.f;
    float* op = out + ((b * OCC + oc) * WW + w) * HH + hq;
    #pragma unroll
    for (int j = 0; j < 8; j++) {
        float4 v = *(float4*)&zbuf[oc * ZBP + hq + (j << 2)];
        v.x += bias; v.y += bias; v.z += bias; v.w += bias;
        s1 += v.x + v.y + v.z + v.w;
        s2 += v.x * v.x + v.y * v.y + v.z * v.z + v.w * v.w;
        *(float4*)&op[j << 2] = v;
    }
    #pragma unroll
    for (int m = 1; m <= 8; m <<= 1) {
        s1 += __shfl_xor_sync(0xffffffffu, s1, m);
        s2 += __shfl_xor_sync(0xffffffffu, s2, m);
    }
    if ((lane & 15) == 0) {
        const int grp = oc >> 2;
        atomicAdd(&g_stats[(b * GG + grp) * 2 + 0], s1);
        atomicAdd(&g_stats[(b * GG + grp) * 2 + 1], s2);
    }
}

// ---------------------------------------------------------------------------
// Kernel C: GroupNorm finalize + ReLU (in place on out)
// ---------------------------------------------------------------------------
__global__ void __launch_bounds__(256) gn_kernel(float* __restrict__ out,
                                                 const float* __restrict__ gn_gamma,
                                                 const float* __restrict__ gn_beta) {
    const int idx = blockIdx.x * 256 + threadIdx.x;
    const int i4 = idx << 2;
    const int oc = (i4 >> 14) & 63;
    const int b = i4 >> 20;
    const int g = oc >> 2;
    const float inv = 1.0f / 65536.0f;
    float s1 = g_stats[(b * GG + g) * 2 + 0];
    float s2 = g_stats[(b * GG + g) * 2 + 1];
    float mean = s1 * inv;
    float var = s2 * inv - mean * mean;
    float sc = gn_gamma[oc] * rsqrtf(var + EPSV);
    float sh = gn_beta[oc] - mean * sc;
    float4* o4 = (float4*)out;
    float4 v = o4[idx];
    v.x = fmaxf(v.x * sc + sh, 0.f);
    v.y = fmaxf(v.y * sc + sh, 0.f);
    v.z = fmaxf(v.z * sc + sh, 0.f);
    v.w = fmaxf(v.w * sc + sh, 0.f);
    o4[idx] = v;
}

// ---------------------------------------------------------------------------
extern "C" void kernel_launch(void* const* d_in, const int* in_sizes, int n_in,
                              void* d_out, int out_size) {
    const float* f        = (const float*)d_in[0];
    const float* offset_w = (const float*)d_in[1];
    const float* offset_b = (const float*)d_in[2];
    const float* bn_gamma = (const float*)d_in[3];
    const float* bn_beta  = (const float*)d_in[4];
    const float* bn_mean  = (const float*)d_in[5];
    const float* bn_var   = (const float*)d_in[6];
    const float* conv_w   = (const float*)d_in[7];
    const float* conv_b   = (const float*)d_in[8];
    const float* gn_gamma = (const float*)d_in[9];
    const float* gn_beta  = (const float*)d_in[10];
    float* out = (float*)d_out;

    const int main_smem = 55296;   // 2x wtB (9216) + 2x dks (18432)
    cudaFuncSetAttribute(main_kernel, cudaFuncAttributeMaxDynamicSharedMemorySize,
                         main_smem);

    wt_pack_kernel<<<(KK * CC * (OCC / 2) + 255) / 256, 256>>>(conv_w);

    offset_kernel<<<BB * WW, 128>>>(f, offset_w, offset_b, bn_gamma, bn_beta,
                                    bn_mean, bn_var);

    main_kernel<<<BB * WW, 256, main_smem>>>(conv_b, out);

    gn_kernel<<<(BB * OCC * WW * HH / 4) / 256, 256>>>(out, gn_gamma, gn_beta);
}

// round 14
// speedup vs baseline: 3.0868x; 1.0003x over previous
#include <cuda_runtime.h>
#include <cuda_fp16.h>
#include <math.h>

#define BB 4
#define CC 64
#define WW 128
#define HH 128
#define KK 9
#define OCC 64
#define GG 16
#define EPSV 1e-5f

// Scratch (static device globals — no allocation allowed)
// Paired fp16 NHWC: g_fTh2[((b*W+y)*H+x)*128 + c*2 + {0,1}] = (f[y][x][c], f[y][min(x+1,127)][c])
__device__ __align__(16) unsigned short g_fTh2[BB * WW * HH * 128];
__device__ __align__(16) unsigned int g_Wt2[KK * CC * (OCC / 2)]; // [k][c][oc/2] half2
__device__ __align__(16) uint4 g_par[BB * KK * WW * HH];    // {base, dy, w01, w23}
__device__ float g_stats[BB * GG * 2];                      // (sum, sumsq)

__device__ __forceinline__ unsigned int s2u(const void* p) {
    unsigned int a;
    asm("{ .reg .u64 t; cvta.to.shared.u64 t, %1; cvt.u32.u64 %0, t; }"
        : "=r"(a) : "l"(p));
    return a;
}

#define LDSM_X4(r0, r1, r2, r3, addr) \
    asm volatile("ldmatrix.sync.aligned.m8n8.x4.shared.b16 {%0,%1,%2,%3}, [%4];" \
                 : "=r"(r0), "=r"(r1), "=r"(r2), "=r"(r3) : "r"(addr))
#define LDSM_X4_T(r0, r1, r2, r3, addr) \
    asm volatile("ldmatrix.sync.aligned.m8n8.x4.trans.shared.b16 {%0,%1,%2,%3}, [%4];" \
                 : "=r"(r0), "=r"(r1), "=r"(r2), "=r"(r3) : "r"(addr))

// ---------------------------------------------------------------------------
// Kernel A: offset conv (9 of 18 oc) + BN + tanh + partial cumsum ->
// packed bilinear params; fused: fp16 PAIRED NHWC copy of f (rows[1] holds
// f[b, :, w, :]), weight packing (blocks 0..71), stat zeroing (block 0).
// grid (B*W), block 128.
// ---------------------------------------------------------------------------
__global__ void __launch_bounds__(128) offset_kernel(
    const float* __restrict__ f, const float* __restrict__ offset_w,
    const float* __restrict__ offset_b, const float* __restrict__ bn_gamma,
    const float* __restrict__ bn_beta, const float* __restrict__ bn_mean,
    const float* __restrict__ bn_var, const float* __restrict__ conv_w) {
    __shared__ float w_s[64 * 108];
    __shared__ float rows[3][8][128];

    const int bw = blockIdx.x;
    const int b = bw >> 7, w = bw & 127;
    const int h = threadIdx.x;

    // fused weight packing: conv_w [oc][c][k] -> g_Wt2 [k][c][oc] half pairs
    if (bw < 72) {
        #pragma unroll
        for (int j = 0; j < 2; j++) {
            int i = bw * 256 + h + j * 128;      // 72*256 = 18432 total
            int k = i / 2048;
            int r = i & 2047;
            int c = r >> 5, oc2 = (r & 31) << 1;
            float w0 = conv_w[(((oc2 << 6) + c) * KK) + k];
            float w1 = conv_w[((((oc2 + 1) << 6) + c) * KK) + k];
            __half2 p = __floats2half2_rn(w0, w1);
            g_Wt2[i] = *(unsigned int*)&p;
        }
    }
    if (bw == 0 && h < BB * GG * 2) g_stats[h] = 0.f;

    for (int i = h; i < 9 * 64 * 9; i += 128) {
        int k = i / 576;
        int r = i - k * 576;
        int c = r / 9, tap = r - (r / 9) * 9;
        w_s[c * 108 + tap * 12 + k] = offset_w[(k * 64 + c) * 9 + tap];
    }

    float acc[9];
    #pragma unroll
    for (int k = 0; k < 9; k++) acc[k] = 0.f;

    const int hn = (h < 127) ? h + 1 : 127;

    for (int cc = 0; cc < 64; cc += 8) {
        __syncthreads();
        for (int i = h; i < 3 * 8 * 128; i += 128) {
            int dy = i / 1024;
            int rem = i - dy * 1024;
            int c = rem >> 7, hh = rem & 127;
            int wr = w + dy - 1;
            float v = 0.f;
            if (wr >= 0 && wr < WW) v = f[((b * CC + cc + c) * WW + wr) * HH + hh];
            rows[dy][c][hh] = v;
        }
        __syncthreads();
        // fused paired transpose: (f[w][h][c], f[w][h+1][c]) for 8 channels
        {
            __half2 hp[8];
            #pragma unroll
            for (int c = 0; c < 8; c++)
                hp[c] = __floats2half2_rn(rows[1][c][h], rows[1][c][hn]);
            unsigned short* dst = &g_fTh2[((b * WW + w) * HH + h) * 128 + cc * 2];
            *(uint4*)dst = *(uint4*)hp;
            *(uint4*)(dst + 8) = *(uint4*)(hp + 4);
        }
        #pragma unroll
        for (int c = 0; c < 8; c++) {
            const float* wb = &w_s[(cc + c) * 108];
            #pragma unroll
            for (int dy = 0; dy < 3; dy++) {
                float vm = (h > 0) ? rows[dy][c][h - 1] : 0.f;
                float vc = rows[dy][c][h];
                float vp = (h < 127) ? rows[dy][c][h + 1] : 0.f;
                #pragma unroll
                for (int dx = 0; dx < 3; dx++) {
                    float v = (dx == 0) ? vm : ((dx == 1) ? vc : vp);
                    const float* wp = wb + (dy * 3 + dx) * 12;
                    float4 w0 = *(const float4*)(wp);
                    float4 w1 = *(const float4*)(wp + 4);
                    float w8 = wp[8];
                    acc[0] = fmaf(v, w0.x, acc[0]);
                    acc[1] = fmaf(v, w0.y, acc[1]);
                    acc[2] = fmaf(v, w0.z, acc[2]);
                    acc[3] = fmaf(v, w0.w, acc[3]);
                    acc[4] = fmaf(v, w1.x, acc[4]);
                    acc[5] = fmaf(v, w1.y, acc[5]);
                    acc[6] = fmaf(v, w1.z, acc[6]);
                    acc[7] = fmaf(v, w1.w, acc[7]);
                    acc[8] = fmaf(v, w8, acc[8]);
                }
            }
        }
    }

    float off[9];
    #pragma unroll
    for (int k = 0; k < 9; k++) {
        float sc = bn_gamma[k] * rsqrtf(bn_var[k] + EPSV);
        off[k] = tanhf((acc[k] + offset_b[k] - bn_mean[k]) * sc + bn_beta[k]);
    }
    float cum[9];
    cum[4] = 0.f;
    cum[0] = off[0];
    cum[8] = off[8];
    cum[5] = off[5];
    cum[6] = cum[5] + off[6];
    cum[7] = cum[6] + off[7];
    cum[3] = off[3];
    cum[2] = cum[3] + off[2];
    cum[1] = cum[2] + off[1];

    #pragma unroll
    for (int k = 0; k < 9; k++) {
        float ys = (float)w + cum[k];
        float xs = (float)h + (-5.0f + 1.125f * (float)k);   // linspace(-5,4,9)
        int y0 = (int)floorf(ys);
        y0 = max(0, min(y0, WW - 1));
        int y1 = min(y0 + 1, WW - 1);
        int x0 = (int)floorf(xs);
        x0 = max(0, min(x0, HH - 1));
        int x1 = min(x0 + 1, HH - 1);
        float wy1 = (float)y1 - ys;
        float wy0 = ys - (float)y0;
        float wx1 = (float)x1 - xs;
        float wx0 = xs - (float)x0;
        uint4 pr;
        pr.x = (unsigned int)((((b * WW + y0) * HH) + x0) * 128);  // halves
        pr.y = (unsigned int)((y1 - y0) * 16384);                  // dy in halves
        __half2 w01 = __floats2half2_rn(wy1 * wx1, wy1 * wx0);
        __half2 w23 = __floats2half2_rn(wy0 * wx1, wy0 * wx0);
        pr.z = *(unsigned int*)&w01;
        pr.w = *(unsigned int*)&w23;
        g_par[((b * KK + k) * WW + w) * HH + h] = pr;
    }
}

// ---------------------------------------------------------------------------
// Kernel B: bilinear gather (paired fp16 source: ONE LDG.128 per y-row gives
// both x corners for 4 channels) + FP16 tensor-core GEMM (ldmatrix) + GN
// partial sums. grid (B*W), block 256 (8 warps), occ 4, double-buffered.
// smem bytes: [0,9216) wtB_0 | [9216,18432) wtB_1
//             [18432,36864) dks_0 [h][c] pitch 72 halves | [36864,55296) dks_1
// epilogue zbuf (64*132 floats) aliases the front, after a sync.
// ---------------------------------------------------------------------------
#define DKPH 72
#define ZBP 132

__global__ void __launch_bounds__(256, 4) main_kernel(
    const float* __restrict__ conv_b, float* __restrict__ out) {
    extern __shared__ char smc[];
    float* zbuf = (float*)smc;                         // epilogue: 64*132 floats

    const int bw = blockIdx.x;
    const int b = bw >> 7, w = bw & 127;
    const int tid = threadIdx.x;
    const int lane = tid & 31;
    const int wid = tid >> 5;
    const int g = lane >> 2, t = lane & 3;
    const int h0 = (wid & 3) << 5;        // m32 tile
    const int n0 = (wid >> 2) << 5;       // n32 tile

    const unsigned int smem_u32 = s2u(smc);

    // ldmatrix per-lane address offsets (bytes); mat = lane>>3
    const int mat = lane >> 3;
    const int mrow = ((mat & 1) << 3) | (lane & 7);
    const int mcol = (mat >> 1) << 3;                  // halves
    const int aoff = (h0 + mrow) * 144 + mcol * 2;     // A: dks rows
    const int boff = mrow * 144 + (n0 + mcol) * 2;     // B: wt k-rows

    float acc[2][4][4];
    #pragma unroll
    for (int mi = 0; mi < 2; mi++)
        #pragma unroll
        for (int nj = 0; nj < 4; nj++)
            #pragma unroll
            for (int j = 0; j < 4; j++) acc[mi][nj][j] = 0.f;

    const int cq8 = (tid & 15) << 3;       // paired-half offset (4 channels)
    const int cq4 = (tid & 15) << 2;       // dks half offset (4 channels)

    for (int k = 0; k < KK; k++) {
        const int par = k & 1;
        unsigned int* wt2 = (unsigned int*)(smc + par * 9216);
        unsigned short* dksh = (unsigned short*)(smc + 18432 + par * 18432);
        const unsigned int wt32 = smem_u32 + par * 9216;
        const unsigned int dk32 = smem_u32 + 18432 + par * 18432;

        // stage weights: exactly 512 uint4s; dst row pitch 9 uint4 (144 B)
        #pragma unroll
        for (int j = 0; j < 2; j++) {
            int i4 = tid + (j << 8);                 // 0..511
            int row = i4 >> 3, col = i4 & 7;
            *((uint4*)wt2 + row * 9 + col) = ((const uint4*)g_Wt2)[(k << 9) + i4];
        }
        // gather -> dksh[h][c] fp16 (fp32 interpolation, paired corners)
        const int pbase = ((b * KK + k) * WW + w) * HH;
        #pragma unroll
        for (int pass = 0; pass < 8; pass++) {
            const int hg = (tid >> 4) + (pass << 4);
            const uint4 pr = __ldg(&g_par[pbase + hg]);
            const int base = (int)pr.x + cq8;
            const int dy = (int)pr.y;
            const __half2 hw01 = *(const __half2*)&pr.z;
            const __half2 hw23 = *(const __half2*)&pr.w;
            const float w00 = __low2float(hw01), w01f = __high2float(hw01);
            const float w10 = __low2float(hw23), w11f = __high2float(hw23);
            // y0 row: 4 channels x (x0,x1) pairs in one LDG.128
            uint4 A0 = *(const uint4*)&g_fTh2[base];
            uint4 A1 = *(const uint4*)&g_fTh2[base + dy];
            float2 p0 = __half22float2(*(__half2*)&A0.x);   // c0: (lo=x0, hi=x1)
            float2 p1 = __half22float2(*(__half2*)&A0.y);
            float2 p2 = __half22float2(*(__half2*)&A0.z);
            float2 p3 = __half22float2(*(__half2*)&A0.w);
            float rx = p0.x * w00, ry = p1.x * w00, rz = p2.x * w00, rw = p3.x * w00;
            rx = fmaf(p0.y, w01f, rx); ry = fmaf(p1.y, w01f, ry);
            rz = fmaf(p2.y, w01f, rz); rw = fmaf(p3.y, w01f, rw);
            p0 = __half22float2(*(__half2*)&A1.x);
            p1 = __half22float2(*(__half2*)&A1.y);
            p2 = __half22float2(*(__half2*)&A1.z);
            p3 = __half22float2(*(__half2*)&A1.w);
            rx = fmaf(p0.x, w10, rx); ry = fmaf(p1.x, w10, ry);
            rz = fmaf(p2.x, w10, rz); rw = fmaf(p3.x, w10, rw);
            rx = fmaf(p0.y, w11f, rx); ry = fmaf(p1.y, w11f, ry);
            rz = fmaf(p2.y, w11f, rz); rw = fmaf(p3.y, w11f, rw);
            __half2 q0 = __floats2half2_rn(rx, ry);   // low = even c
            __half2 q1 = __floats2half2_rn(rz, rw);
            uint2 pk;
            pk.x = *(unsigned int*)&q0;
            pk.y = *(unsigned int*)&q1;
            *(uint2*)&dksh[hg * DKPH + cq4] = pk;
        }
        __syncthreads();
        // MMA: warp tile m32 x n32, K=64 halves in 4 k16 chunks, ldmatrix frags
        #pragma unroll
        for (int kc = 0; kc < 4; kc++) {
            unsigned int a0[4], a1[4], bb0[4], bb1[4];
            const unsigned int aa = dk32 + aoff + kc * 32;
            LDSM_X4(a0[0], a0[1], a0[2], a0[3], aa);
            LDSM_X4(a1[0], a1[1], a1[2], a1[3], aa + 16 * 144);
            const unsigned int ba = wt32 + boff + kc * 2304;   // 16 k-rows
            LDSM_X4_T(bb0[0], bb0[1], bb0[2], bb0[3], ba);
            LDSM_X4_T(bb1[0], bb1[1], bb1[2], bb1[3], ba + 32);
            #pragma unroll
            for (int nj = 0; nj < 4; nj++) {
                const unsigned int b0 = (nj < 2) ? bb0[(nj & 1) << 1] : bb1[(nj & 1) << 1];
                const unsigned int b1 = (nj < 2) ? bb0[((nj & 1) << 1) + 1]
                                                 : bb1[((nj & 1) << 1) + 1];
                #pragma unroll
                for (int mi = 0; mi < 2; mi++) {
                    unsigned int* a = mi ? a1 : a0;
                    asm("mma.sync.aligned.m16n8k16.row.col.f32.f16.f16.f32 "
                        "{%0,%1,%2,%3}, {%4,%5,%6,%7}, {%8,%9}, {%0,%1,%2,%3};"
                        : "+f"(acc[mi][nj][0]), "+f"(acc[mi][nj][1]),
                          "+f"(acc[mi][nj][2]), "+f"(acc[mi][nj][3])
                        : "r"(a[0]), "r"(a[1]), "r"(a[2]), "r"(a[3]),
                          "r"(b0), "r"(b1));
                }
            }
        }
    }

    // epilogue: fragments -> zbuf[oc][h] -> coalesced out + GN stats
    __syncthreads();     // all MMA reads of dks/wt2 done before aliasing as zbuf
    #pragma unroll
    for (int mi = 0; mi < 2; mi++) {
        #pragma unroll
        for (int nj = 0; nj < 4; nj++) {
            const int oc = n0 + (nj << 3) + (t << 1);
            const int hh = h0 + (mi << 4) + g;
            zbuf[oc * ZBP + hh] = acc[mi][nj][0];
            zbuf[(oc + 1) * ZBP + hh] = acc[mi][nj][1];
            zbuf[oc * ZBP + hh + 8] = acc[mi][nj][2];
            zbuf[(oc + 1) * ZBP + hh + 8] = acc[mi][nj][3];
        }
    }
    __syncthreads();
    const int oc = tid >> 2;
    const int hq = (tid & 3) << 5;
    const float bias = conv_b[oc];
    float s1 = 0.f, s2 = 0.f;
    float* op = out + ((b * OCC + oc) * WW + w) * HH + hq;
    #pragma unroll
    for (int j = 0; j < 8; j++) {
        float4 v = *(float4*)&zbuf[oc * ZBP + hq + (j << 2)];
        v.x += bias; v.y += bias; v.z += bias; v.w += bias;
        s1 += v.x + v.y + v.z + v.w;
        s2 += v.x * v.x + v.y * v.y + v.z * v.z + v.w * v.w;
        *(float4*)&op[j << 2] = v;
    }
    #pragma unroll
    for (int m = 1; m <= 8; m <<= 1) {
        s1 += __shfl_xor_sync(0xffffffffu, s1, m);
        s2 += __shfl_xor_sync(0xffffffffu, s2, m);
    }
    if ((lane & 15) == 0) {
        const int grp = oc >> 2;
        atomicAdd(&g_stats[(b * GG + grp) * 2 + 0], s1);
        atomicAdd(&g_stats[(b * GG + grp) * 2 + 1], s2);
    }
}

// ---------------------------------------------------------------------------
// Kernel C: GroupNorm finalize + ReLU (in place on out)
// ---------------------------------------------------------------------------
__global__ void __launch_bounds__(256) gn_kernel(float* __restrict__ out,
                                                 const float* __restrict__ gn_gamma,
                                                 const float* __restrict__ gn_beta) {
    const int idx = blockIdx.x * 256 + threadIdx.x;
    const int i4 = idx << 2;
    const int oc = (i4 >> 14) & 63;
    const int b = i4 >> 20;
    const int g = oc >> 2;
    const float inv = 1.0f / 65536.0f;
    float s1 = g_stats[(b * GG + g) * 2 + 0];
    float s2 = g_stats[(b * GG + g) * 2 + 1];
    float mean = s1 * inv;
    float var = s2 * inv - mean * mean;
    float sc = gn_gamma[oc] * rsqrtf(var + EPSV);
    float sh = gn_beta[oc] - mean * sc;
    float4* o4 = (float4*)out;
    float4 v = o4[idx];
    v.x = fmaxf(v.x * sc + sh, 0.f);
    v.y = fmaxf(v.y * sc + sh, 0.f);
    v.z = fmaxf(v.z * sc + sh, 0.f);
    v.w = fmaxf(v.w * sc + sh, 0.f);
    o4[idx] = v;
}

// ---------------------------------------------------------------------------
extern "C" void kernel_launch(void* const* d_in, const int* in_sizes, int n_in,
                              void* d_out, int out_size) {
    const float* f        = (const float*)d_in[0];
    const float* offset_w = (const float*)d_in[1];
    const float* offset_b = (const float*)d_in[2];
    const float* bn_gamma = (const float*)d_in[3];
    const float* bn_beta  = (const float*)d_in[4];
    const float* bn_mean  = (const float*)d_in[5];
    const float* bn_var   = (const float*)d_in[6];
    const float* conv_w   = (const float*)d_in[7];
    const float* conv_b   = (const float*)d_in[8];
    const float* gn_gamma = (const float*)d_in[9];
    const float* gn_beta  = (const float*)d_in[10];
    float* out = (float*)d_out;

    const int main_smem = 55296;   // 2x wtB (9216) + 2x dks (18432)
    cudaFuncSetAttribute(main_kernel, cudaFuncAttributeMaxDynamicSharedMemorySize,
                         main_smem);

    offset_kernel<<<BB * WW, 128>>>(f, offset_w, offset_b, bn_gamma, bn_beta,
                                    bn_mean, bn_var, conv_w);

    main_kernel<<<BB * WW, 256, main_smem>>>(conv_b, out);

    gn_kernel<<<(BB * OCC * WW * HH / 4) / 256, 256>>>(out, gn_gamma, gn_beta);
}